// round 5
// baseline (speedup 1.0000x reference)
#include <cuda_runtime.h>
#include <cuda_fp16.h>
#include <stdint.h>

#define Bz 4
#define Nn 4096
#define Mm 4096
#define Cc 256

// ---------------- persistent device scratch (no runtime alloc) ----------------
__device__ __align__(16) float2 g_sl0[Bz][Nn];  // original-order baked coords
__device__ __align__(16) float2 g_tl0[Bz][Mm];
__device__ unsigned char g_sok0[Bz][Nn];
__device__ int g_tkey[Bz][Mm];
__device__ int g_skey[Bz][Nn];
__device__ int g_tperm[Bz][Mm];                 // sorted pos -> orig idx
__device__ int g_sperm[Bz][Nn];

// SORTED packed arrays: (x, y, dual, 0)
__device__ __align__(16) float4 g_sv4[Bz][Nn];  // source: coords + v
__device__ __align__(16) float4 g_tu4[Bz][Mm];  // target: coords + u
__device__ unsigned char g_sok[Bz][Nn];
__device__ unsigned char g_has[Bz][Mm];
__device__ __align__(16) float4 g_sbb[Bz][Nn / 32];   // 32-pt chunk bboxes
__device__ __align__(16) float4 g_tbb[Bz][Mm / 32];
__device__ __align__(16) float4 g_sbbs[Bz][16];       // 256-pt super bboxes
__device__ __align__(16) float4 g_tbbs[Bz][16];
__device__ int g_cnt0[3 * Bz];
__device__ __align__(16) __half g_fT[Bz][Cc][Nn];     // feats fp16, transposed, sorted n

// ---------------- mask dtype auto-detect ------------------------------------
__device__ __forceinline__ int detect_fmt(const unsigned* w) {
    bool sawF = false, sawU = false;
    for (int i = 0; i < 64; i++) {
        unsigned v = w[i];
        if (v == 0x3F800000u) sawF = true;
        else if (v > 1u) {
            unsigned b0 = v & 255u, b1 = (v >> 8) & 255u, b2 = (v >> 16) & 255u, b3 = v >> 24;
            if (b0 <= 1u && b1 <= 1u && b2 <= 1u && b3 <= 1u) sawU = true;
            else sawF = true;
        }
    }
    if (sawF) return 2;
    if (sawU) return 0;
    return 1;
}
__device__ __forceinline__ bool read_mask(const void* p, int i, int fmt) {
    if (fmt == 0) return ((const unsigned char*)p)[i] != 0;
    if (fmt == 1) return ((const int*)p)[i] != 0;
    return ((const float*)p)[i] != 0.0f;
}

__device__ __forceinline__ unsigned spread4(unsigned x) {
    x &= 15u; x = (x | (x << 2)) & 0x33u; x = (x | (x << 1)) & 0x55u; return x;
}
__device__ __forceinline__ int morton_key(float x, float y) {
    int cx = (int)(x * 16.0f); cx = cx < 0 ? 0 : (cx > 15 ? 15 : cx);
    int cy = (int)(y * 16.0f); cy = cy < 0 ? 0 : (cy > 15 ? 15 : cy);
    return (int)(spread4((unsigned)cx) | (spread4((unsigned)cy) << 1));
}

// ---------------- prep -------------------------------------------------------
__global__ void prep_kernel(const float* __restrict__ slocs,
                            const float* __restrict__ tlocs,
                            const void* __restrict__ smask,
                            const void* __restrict__ tmask) {
    __shared__ int sf[2];
    if (threadIdx.x == 0) {
        sf[0] = detect_fmt((const unsigned*)smask);
        sf[1] = detect_fmt((const unsigned*)tmask);
    }
    __syncthreads();
    int i = blockIdx.x * blockDim.x + threadIdx.x;
    if (blockIdx.x == 0 && threadIdx.x < 3 * Bz) g_cnt0[threadIdx.x] = 0;
    if (i >= Bz * Nn) return;
    int b = i / Nn, n = i % Nn;

    bool sok = read_mask(smask, i, sf[0]);
    float sx = slocs[2 * i], sy = slocs[2 * i + 1];
    g_sl0[b][n] = make_float2(sok ? sx : -1e18f, sy);
    g_sok0[b][n] = sok ? 1 : 0;
    g_skey[b][n] = sok ? morton_key(sx, sy) : 256;

    bool tok = read_mask(tmask, i, sf[1]);
    float tx = tlocs[2 * i], ty = tlocs[2 * i + 1];
    g_tl0[b][n] = make_float2(tok ? tx : 1e18f, ty);
    g_tkey[b][n] = tok ? morton_key(tx, ty) : 256;
}

// ---------------- bitonic sort of (key<<12 | idx) -----------------------------
__global__ __launch_bounds__(1024) void sort_kernel() {
    __shared__ unsigned sk[4096];
    int side = blockIdx.x, b = blockIdx.y, tid = threadIdx.x;
    for (int i = tid; i < 4096; i += 1024) {
        int key = side ? g_skey[b][i] : g_tkey[b][i];
        sk[i] = ((unsigned)key << 12) | (unsigned)i;
    }
    __syncthreads();
    for (int k = 2; k <= 4096; k <<= 1) {
        for (int j = k >> 1; j >= 1; j >>= 1) {
            for (int i = tid; i < 4096; i += 1024) {
                int l = i ^ j;
                if (l > i) {
                    unsigned a = sk[i], c = sk[l];
                    bool up = ((i & k) == 0);
                    if ((a > c) == up) { sk[i] = c; sk[l] = a; }
                }
            }
            __syncthreads();
        }
    }
    for (int i = tid; i < 4096; i += 1024) {
        int idx = (int)(sk[i] & 0xFFFu);
        if (side) g_sperm[b][i] = idx; else g_tperm[b][i] = idx;
    }
}

// ---------------- scatter to sorted order + chunk & super bboxes -------------
// grid (16, Bz, 2); block 256 = 8 warps = 8 chunks = 1 superchunk
__global__ void scatter_kernel() {
    __shared__ float4 sCB[8];
    int b = blockIdx.y, side = blockIdx.z;
    int i = blockIdx.x * 256 + threadIdx.x;
    int warp = threadIdx.x >> 5, lane = threadIdx.x & 31;
    float2 p;
    if (side == 0) {
        int idx = g_tperm[b][i];
        p = g_tl0[b][idx];
        g_tu4[b][i] = make_float4(p.x, p.y, 0.0f, 0.0f);
    } else {
        int idx = g_sperm[b][i];
        p = g_sl0[b][idx];
        g_sv4[b][i] = make_float4(p.x, p.y, 0.0f, 0.0f);
        g_sok[b][i] = g_sok0[b][idx];
    }
    float mnx = p.x, mxx = p.x, mny = p.y, mxy = p.y;
    #pragma unroll
    for (int off = 16; off; off >>= 1) {
        mnx = fminf(mnx, __shfl_xor_sync(0xffffffffu, mnx, off));
        mxx = fmaxf(mxx, __shfl_xor_sync(0xffffffffu, mxx, off));
        mny = fminf(mny, __shfl_xor_sync(0xffffffffu, mny, off));
        mxy = fmaxf(mxy, __shfl_xor_sync(0xffffffffu, mxy, off));
    }
    if (lane == 0) {
        float4 bb = make_float4(mnx, mny, mxx, mxy);
        sCB[warp] = bb;
        int chunk = i >> 5;
        if (side == 0) g_tbb[b][chunk] = bb; else g_sbb[b][chunk] = bb;
    }
    __syncthreads();
    if (threadIdx.x == 0) {
        float4 u = sCB[0];
        #pragma unroll
        for (int w = 1; w < 8; w++) {
            float4 c = sCB[w];
            u.x = fminf(u.x, c.x); u.y = fminf(u.y, c.y);
            u.z = fmaxf(u.z, c.z); u.w = fmaxf(u.w, c.w);
        }
        if (side == 0) g_tbbs[b][blockIdx.x] = u; else g_sbbs[b][blockIdx.x] = u;
    }
}

// ---------------- feats f32 [b][orig n][c] -> fp16 [b][c][sorted n] ----------
__global__ void feats_transpose(const float* __restrict__ f) {
    __shared__ float tile[32][33];
    int b = blockIdx.z;
    int n0 = blockIdx.x * 32, c0 = blockIdx.y * 32;
    int tx = threadIdx.x, ty = threadIdx.y;   // 32 x 8
    #pragma unroll
    for (int j = 0; j < 4; j++) {
        int n = n0 + ty + j * 8;
        int on = g_sperm[b][n];
        tile[ty + j * 8][tx] = f[((b * Nn + on) * Cc) + (c0 + tx)];
    }
    __syncthreads();
    #pragma unroll
    for (int j = 0; j < 4; j++) {
        int c = c0 + ty + j * 8;
        g_fT[b][c][n0 + tx] = __float2half(tile[tx][ty + j * 8]);
    }
}

// ---------------- streaming LSE: 8 rows/warp, 2-level bbox skip ---------------
// block 256 = 8 warps x 8 rows = 64 rows; grid (4096/64, Bz)
template <int MODE>
__global__ __launch_bounds__(256) void lse_kernel(int iter) {
    const int b = blockIdx.y;
    const int warp = threadIdx.x >> 5, lane = threadIdx.x & 31;
    const int row0 = blockIdx.x * 64 + warp * 8;
    const float NEG_INV = -1.0f / 0.01000001f;

    __shared__ __align__(16) float4 sBB[128];
    __shared__ __align__(16) float4 sSB[16];
    if (threadIdx.x < 128)
        sBB[threadIdx.x] = (MODE == 0) ? g_sbb[b][threadIdx.x] : g_tbb[b][threadIdx.x];
    if (threadIdx.x < 16)
        sSB[threadIdx.x] = (MODE == 0) ? g_sbbs[b][threadIdx.x] : g_tbbs[b][threadIdx.x];
    __syncthreads();

    float tx[8], ty[8], mx[8], ss[8];
    #pragma unroll
    for (int r = 0; r < 8; r++) {
        float4 p = (MODE == 0) ? g_tu4[b][row0 + r] : g_sv4[b][row0 + r];
        tx[r] = p.x; ty[r] = p.y;
        mx[r] = -1e30f; ss[r] = 0.0f;
    }
    float rmnx = tx[0], rmxx = tx[0], rmny = ty[0], rmxy = ty[0];
    #pragma unroll
    for (int r = 1; r < 8; r++) {
        rmnx = fminf(rmnx, tx[r]); rmxx = fmaxf(rmxx, tx[r]);
        rmny = fminf(rmny, ty[r]); rmxy = fmaxf(rmxy, ty[r]);
    }

    for (int s = 0; s < 16; s++) {
        float4 sb = sSB[s];
        float sdx = fmaxf(fmaxf(sb.x - rmxx, rmnx - sb.z), 0.0f);
        float sdy = fmaxf(fmaxf(sb.y - rmxy, rmny - sb.w), 0.0f);
        if (sdx * sdx + sdy * sdy >= 0.0401f) continue;

        #pragma unroll 1
        for (int c8 = 0; c8 < 8; c8++) {
            int c = s * 8 + c8;
            float4 cb = sBB[c];
            float ddx = fmaxf(fmaxf(cb.x - rmxx, rmnx - cb.z), 0.0f);
            float ddy = fmaxf(fmaxf(cb.y - rmxy, rmny - cb.w), 0.0f);
            if (ddx * ddx + ddy * ddy >= 0.0401f) continue;

            int n = c * 32 + lane;
            float4 q = (MODE == 0) ? g_sv4[b][n] : g_tu4[b][n];
            #pragma unroll
            for (int r = 0; r < 8; r++) {
                float dx = __fadd_rn(tx[r], -q.x);
                float dy = __fadd_rn(ty[r], -q.y);
                float d2 = __fadd_rn(__fmul_rn(dx, dx), __fmul_rn(dy, dy));
                if (d2 < 0.04f) {
                    float x  = __fmaf_rn(d2, NEG_INV, q.z);
                    float dd = x - mx[r];
                    float e  = __expf(-fabsf(dd));
                    if (dd > 0.0f) { ss[r] = __fmaf_rn(ss[r], e, 1.0f); mx[r] = x; }
                    else           { ss[r] += e; }
                }
            }
        }
    }

    #pragma unroll
    for (int off = 16; off; off >>= 1) {
        #pragma unroll
        for (int r = 0; r < 8; r++) {
            float m2 = __shfl_xor_sync(0xffffffffu, mx[r], off);
            float s2 = __shfl_xor_sync(0xffffffffu, ss[r], off);
            float M  = fmaxf(mx[r], m2);
            ss[r] = ss[r] * __expf(mx[r] - M) + s2 * __expf(m2 - M);
            mx[r] = M;
        }
    }

    #pragma unroll
    for (int r = 0; r < 8; r++) {
        if (lane == r) {
            float m = mx[r], s = ss[r];
            int row = row0 + r;
            if (MODE == 0) {
                bool anyvalid = (s > 0.0f);
                float dual = anyvalid ? -(m + __logf(s)) : 1.0e9f;
                if (!anyvalid) atomicAdd(&g_cnt0[iter * Bz + b], 1);
                g_tu4[b][row].z = dual;
                g_has[b][row] = anyvalid ? 1 : 0;
            } else {
                int cnt0 = g_cnt0[iter * Bz + b];
                if (cnt0 > 0) {
                    float M = fmaxf(m, 0.0f);
                    s = s * __expf(m - M) + (float)cnt0 * __expf(0.0f - M);
                    m = M;
                }
                float dual = (s == 0.0f) ? 1.0e9f : -(m + __logf(s));
                g_sv4[b][row].z = g_sok[b][row] ? dual : 0.0f;
            }
        }
    }
}

// ---------------- fused attn-recompute GEMM ----------------------------------
__device__ __forceinline__ void mma16816(float& c0, float& c1, float& c2, float& c3,
                                         unsigned a0, unsigned a1, unsigned a2, unsigned a3,
                                         unsigned b0, unsigned b1) {
    asm volatile(
        "mma.sync.aligned.m16n8k16.row.col.f32.f16.f16.f32 "
        "{%0,%1,%2,%3}, {%4,%5,%6,%7}, {%8,%9}, {%0,%1,%2,%3};\n"
        : "+f"(c0), "+f"(c1), "+f"(c2), "+f"(c3)
        : "r"(a0), "r"(a1), "r"(a2), "r"(a3), "r"(b0), "r"(b1));
}

__device__ __forceinline__ float attn_val(float txx, float tyy, float uu, float4 q) {
    const float NEG_INV = -1.0f / 0.01000001f;
    float dx = __fadd_rn(txx, -q.x);
    float dy = __fadd_rn(tyy, -q.y);
    float d2 = __fadd_rn(__fmul_rn(dx, dx), __fmul_rn(dy, dy));
    if (d2 < 0.04f)
        return __expf(__fadd_rn(__fmaf_rn(d2, NEG_INV, uu), q.z));
    return 0.0f;
}

__device__ __forceinline__ unsigned pack2(float x, float y) {
    __half2 h = __floats2half2_rn(x, y);
    return *reinterpret_cast<unsigned*>(&h);
}

#define GBM 64
#define GBC 128
#define GBK 64
#define SBSTRIDE 72

// 128 threads = 4 warps; warp = 16 m-rows x 128 c-cols; grid (64, 2, Bz)
__global__ __launch_bounds__(128) void gemm_kernel(float* __restrict__ out) {
    const int b  = blockIdx.z;
    const int m0 = blockIdx.x * GBM;
    const int c0 = blockIdx.y * GBC;
    const int warp = threadIdx.x >> 5, lane = threadIdx.x & 31;
    const int gid = lane >> 2, tig = lane & 3;

    __shared__ __align__(16) __half sB[GBC][SBSTRIDE];
    __shared__ __align__(16) float4 sS[GBK];

    float tmnx, tmxx, tmny, tmxy;
    {
        float4 b0 = g_tbb[b][(m0 >> 5) + 0], b1 = g_tbb[b][(m0 >> 5) + 1];
        tmnx = fminf(b0.x, b1.x); tmny = fminf(b0.y, b1.y);
        tmxx = fmaxf(b0.z, b1.z); tmxy = fmaxf(b0.w, b1.w);
    }

    const int rlo = m0 + warp * 16 + gid;
    const int rhi = rlo + 8;
    const float4 plo = g_tu4[b][rlo];
    const float4 phi = g_tu4[b][rhi];
    const bool haslo = g_has[b][rlo] != 0;
    const bool hashi = g_has[b][rhi] != 0;

    float acc[16][4];
    #pragma unroll
    for (int j = 0; j < 16; j++) {
        acc[j][0] = 0.f; acc[j][1] = 0.f; acc[j][2] = 0.f; acc[j][3] = 0.f;
    }

    for (int n0 = 0; n0 < Nn; n0 += GBK) {
        {
            float4 s0 = g_sbb[b][(n0 >> 5) + 0], s1 = g_sbb[b][(n0 >> 5) + 1];
            float smnx = fminf(s0.x, s1.x), smny = fminf(s0.y, s1.y);
            float smxx = fmaxf(s0.z, s1.z), smxy = fmaxf(s0.w, s1.w);
            float ddx = fmaxf(fmaxf(smnx - tmxx, tmnx - smxx), 0.0f);
            float ddy = fmaxf(fmaxf(smny - tmxy, tmny - smxy), 0.0f);
            if (ddx * ddx + ddy * ddy >= 0.0401f) continue;
        }
        __syncthreads();
        {
            int idx = threadIdx.x;                 // 128 threads, 1024 uint4
            #pragma unroll
            for (int t = 0; t < 8; t++, idx += 128) {
                int row = idx >> 3, ch = idx & 7;
                const uint4* src = reinterpret_cast<const uint4*>(&g_fT[b][c0 + row][n0]) + ch;
                *reinterpret_cast<uint4*>(&sB[row][ch * 8]) = *src;
            }
        }
        if (threadIdx.x < GBK) sS[threadIdx.x] = g_sv4[b][n0 + threadIdx.x];
        __syncthreads();

        #pragma unroll
        for (int kf = 0; kf < 4; kf++) {
            const int kb = kf * 16 + 2 * tig;
            float4 qa = sS[kb];
            float4 qb = sS[kb + 1];
            float4 qc = sS[kb + 8];
            float4 qd = sS[kb + 9];

            unsigned a0 = pack2(attn_val(plo.x, plo.y, plo.z, qa), attn_val(plo.x, plo.y, plo.z, qb));
            unsigned a1 = pack2(attn_val(phi.x, phi.y, phi.z, qa), attn_val(phi.x, phi.y, phi.z, qb));
            unsigned a2 = pack2(attn_val(plo.x, plo.y, plo.z, qc), attn_val(plo.x, plo.y, plo.z, qd));
            unsigned a3 = pack2(attn_val(phi.x, phi.y, phi.z, qc), attn_val(phi.x, phi.y, phi.z, qd));

            #pragma unroll
            for (int j = 0; j < 16; j++) {
                const __half* brow = &sB[j * 8 + gid][kf * 16 + 2 * tig];
                unsigned b0 = *reinterpret_cast<const unsigned*>(brow);
                unsigned b1 = *reinterpret_cast<const unsigned*>(brow + 8);
                mma16816(acc[j][0], acc[j][1], acc[j][2], acc[j][3],
                         a0, a1, a2, a3, b0, b1);
            }
        }
    }

    const int orlo = g_tperm[b][rlo];
    const int orhi = g_tperm[b][rhi];
    #pragma unroll
    for (int j = 0; j < 16; j++) {
        int c = c0 + j * 8 + 2 * tig;
        float2 vlo = haslo ? make_float2(acc[j][0], acc[j][1]) : make_float2(0.f, 0.f);
        float2 vhi = hashi ? make_float2(acc[j][2], acc[j][3]) : make_float2(0.f, 0.f);
        *reinterpret_cast<float2*>(&out[((b * Mm + orlo) * Cc) + c]) = vlo;
        *reinterpret_cast<float2*>(&out[((b * Mm + orhi) * Cc) + c]) = vhi;
    }
}

// ------------------------------- launch ---------------------------------------
extern "C" void kernel_launch(void* const* d_in, const int* in_sizes, int n_in,
                              void* d_out, int out_size) {
    const float* feats = (const float*)d_in[0];
    const float* slocs = (const float*)d_in[1];
    const float* tlocs = (const float*)d_in[2];
    const void*  smask = d_in[3];
    const void*  tmask = d_in[4];
    float* out = (float*)d_out;

    prep_kernel<<<(Bz * Nn + 255) / 256, 256>>>(slocs, tlocs, smask, tmask);
    sort_kernel<<<dim3(2, Bz), 1024>>>();
    scatter_kernel<<<dim3(16, Bz, 2), 256>>>();
    feats_transpose<<<dim3(Nn / 32, Cc / 32, Bz), dim3(32, 8)>>>(feats);

    for (int it = 0; it < 3; it++) {
        lse_kernel<0><<<dim3(Mm / 64, Bz), 256>>>(it);
        lse_kernel<1><<<dim3(Nn / 64, Bz), 256>>>(it);
    }

    gemm_kernel<<<dim3(Mm / GBM, Cc / GBC, Bz), 128>>>(out);
}

// round 6
// speedup vs baseline: 1.0666x; 1.0666x over previous
#include <cuda_runtime.h>
#include <cuda_fp16.h>
#include <stdint.h>

#define Bz 4
#define Nn 4096
#define Mm 4096
#define Cc 256
#define NGRP (Mm / 4)   // 4-row groups per side

// ---------------- persistent device scratch (no runtime alloc) ----------------
__device__ __align__(16) float2 g_sl0[Bz][Nn];
__device__ __align__(16) float2 g_tl0[Bz][Mm];
__device__ unsigned char g_sok0[Bz][Nn];
__device__ int g_tkey[Bz][Mm];
__device__ int g_skey[Bz][Nn];
__device__ int g_tperm[Bz][Mm];
__device__ int g_sperm[Bz][Nn];

// SORTED packed arrays: (x, y, dual, 0)
__device__ __align__(16) float4 g_sv4[Bz][Nn];
__device__ __align__(16) float4 g_tu4[Bz][Mm];
__device__ unsigned char g_sok[Bz][Nn];
__device__ unsigned char g_has[Bz][Mm];
__device__ __align__(16) float4 g_sbb[Bz][Nn / 32];
__device__ __align__(16) float4 g_tbb[Bz][Mm / 32];
__device__ int g_cnt0[3 * Bz];
__device__ __align__(16) __half g_fT[Bz][Cc][Nn];

// chunk include-lists: per 4-row group, uint8 chunk ids (<=128)
__device__ __align__(16) unsigned char g_lstT[Bz][NGRP][128];  // target groups -> source chunks
__device__ __align__(16) unsigned char g_lstS[Bz][NGRP][128];  // source groups -> target chunks
__device__ int g_lcntT[Bz][NGRP];
__device__ int g_lcntS[Bz][NGRP];

// ---------------- mask dtype auto-detect ------------------------------------
__device__ __forceinline__ int detect_fmt(const unsigned* w) {
    bool sawF = false, sawU = false;
    for (int i = 0; i < 64; i++) {
        unsigned v = w[i];
        if (v == 0x3F800000u) sawF = true;
        else if (v > 1u) {
            unsigned b0 = v & 255u, b1 = (v >> 8) & 255u, b2 = (v >> 16) & 255u, b3 = v >> 24;
            if (b0 <= 1u && b1 <= 1u && b2 <= 1u && b3 <= 1u) sawU = true;
            else sawF = true;
        }
    }
    if (sawF) return 2;
    if (sawU) return 0;
    return 1;
}
__device__ __forceinline__ bool read_mask(const void* p, int i, int fmt) {
    if (fmt == 0) return ((const unsigned char*)p)[i] != 0;
    if (fmt == 1) return ((const int*)p)[i] != 0;
    return ((const float*)p)[i] != 0.0f;
}

__device__ __forceinline__ unsigned spread4(unsigned x) {
    x &= 15u; x = (x | (x << 2)) & 0x33u; x = (x | (x << 1)) & 0x55u; return x;
}
__device__ __forceinline__ int morton_key(float x, float y) {
    int cx = (int)(x * 16.0f); cx = cx < 0 ? 0 : (cx > 15 ? 15 : cx);
    int cy = (int)(y * 16.0f); cy = cy < 0 ? 0 : (cy > 15 ? 15 : cy);
    return (int)(spread4((unsigned)cx) | (spread4((unsigned)cy) << 1));
}

// ---------------- prep -------------------------------------------------------
__global__ void prep_kernel(const float* __restrict__ slocs,
                            const float* __restrict__ tlocs,
                            const void* __restrict__ smask,
                            const void* __restrict__ tmask) {
    __shared__ int sf[2];
    if (threadIdx.x == 0) {
        sf[0] = detect_fmt((const unsigned*)smask);
        sf[1] = detect_fmt((const unsigned*)tmask);
    }
    __syncthreads();
    int i = blockIdx.x * blockDim.x + threadIdx.x;
    if (blockIdx.x == 0 && threadIdx.x < 3 * Bz) g_cnt0[threadIdx.x] = 0;
    if (i >= Bz * Nn) return;
    int b = i / Nn, n = i % Nn;

    bool sok = read_mask(smask, i, sf[0]);
    float sx = slocs[2 * i], sy = slocs[2 * i + 1];
    g_sl0[b][n] = make_float2(sok ? sx : -1e18f, sy);
    g_sok0[b][n] = sok ? 1 : 0;
    g_skey[b][n] = sok ? morton_key(sx, sy) : 256;

    bool tok = read_mask(tmask, i, sf[1]);
    float tx = tlocs[2 * i], ty = tlocs[2 * i + 1];
    g_tl0[b][n] = make_float2(tok ? tx : 1e18f, ty);
    g_tkey[b][n] = tok ? morton_key(tx, ty) : 256;
}

// ---------------- bitonic sort of (key<<12 | idx) -----------------------------
__global__ __launch_bounds__(1024) void sort_kernel() {
    __shared__ unsigned sk[4096];
    int side = blockIdx.x, b = blockIdx.y, tid = threadIdx.x;
    for (int i = tid; i < 4096; i += 1024) {
        int key = side ? g_skey[b][i] : g_tkey[b][i];
        sk[i] = ((unsigned)key << 12) | (unsigned)i;
    }
    __syncthreads();
    for (int k = 2; k <= 4096; k <<= 1) {
        for (int j = k >> 1; j >= 1; j >>= 1) {
            for (int i = tid; i < 4096; i += 1024) {
                int l = i ^ j;
                if (l > i) {
                    unsigned a = sk[i], c = sk[l];
                    bool up = ((i & k) == 0);
                    if ((a > c) == up) { sk[i] = c; sk[l] = a; }
                }
            }
            __syncthreads();
        }
    }
    for (int i = tid; i < 4096; i += 1024) {
        int idx = (int)(sk[i] & 0xFFFu);
        if (side) g_sperm[b][i] = idx; else g_tperm[b][i] = idx;
    }
}

// ---------------- scatter to sorted order + chunk bboxes ---------------------
__global__ void scatter_kernel() {
    int b = blockIdx.y, side = blockIdx.z;
    int i = blockIdx.x * 256 + threadIdx.x;
    int lane = threadIdx.x & 31;
    float2 p;
    if (side == 0) {
        int idx = g_tperm[b][i];
        p = g_tl0[b][idx];
        g_tu4[b][i] = make_float4(p.x, p.y, 0.0f, 0.0f);
    } else {
        int idx = g_sperm[b][i];
        p = g_sl0[b][idx];
        g_sv4[b][i] = make_float4(p.x, p.y, 0.0f, 0.0f);
        g_sok[b][i] = g_sok0[b][idx];
    }
    float mnx = p.x, mxx = p.x, mny = p.y, mxy = p.y;
    #pragma unroll
    for (int off = 16; off; off >>= 1) {
        mnx = fminf(mnx, __shfl_xor_sync(0xffffffffu, mnx, off));
        mxx = fmaxf(mxx, __shfl_xor_sync(0xffffffffu, mxx, off));
        mny = fminf(mny, __shfl_xor_sync(0xffffffffu, mny, off));
        mxy = fmaxf(mxy, __shfl_xor_sync(0xffffffffu, mxy, off));
    }
    if (lane == 0) {
        int chunk = i >> 5;
        float4 bb = make_float4(mnx, mny, mxx, mxy);
        if (side == 0) g_tbb[b][chunk] = bb; else g_sbb[b][chunk] = bb;
    }
}

// ---------------- build per-group chunk include-lists ------------------------
// grid (NGRP/8, Bz, 2); block 256 = 8 warps; warp = one 4-row group
__global__ __launch_bounds__(256) void build_lists() {
    int b = blockIdx.y, side = blockIdx.z;     // side 0: target groups, 1: source groups
    int warp = threadIdx.x >> 5, lane = threadIdx.x & 31;
    int grp = blockIdx.x * 8 + warp;
    int row0 = grp * 4;

    float rmnx = 1e30f, rmxx = -1e30f, rmny = 1e30f, rmxy = -1e30f;
    #pragma unroll
    for (int r = 0; r < 4; r++) {
        float4 p = (side == 0) ? g_tu4[b][row0 + r] : g_sv4[b][row0 + r];
        rmnx = fminf(rmnx, p.x); rmxx = fmaxf(rmxx, p.x);
        rmny = fminf(rmny, p.y); rmxy = fmaxf(rmxy, p.y);
    }

    unsigned char* lst = (side == 0) ? g_lstT[b][grp] : g_lstS[b][grp];
    int base = 0;
    #pragma unroll
    for (int t = 0; t < 4; t++) {
        int c = t * 32 + lane;
        float4 cb = (side == 0) ? g_sbb[b][c] : g_tbb[b][c];
        float ddx = fmaxf(fmaxf(cb.x - rmxx, rmnx - cb.z), 0.0f);
        float ddy = fmaxf(fmaxf(cb.y - rmxy, rmny - cb.w), 0.0f);
        bool inc = (ddx * ddx + ddy * ddy < 0.0401f);
        unsigned mask = __ballot_sync(0xffffffffu, inc);
        if (inc) lst[base + __popc(mask & ((1u << lane) - 1u))] = (unsigned char)c;
        base += __popc(mask);
    }
    if (lane == 0) {
        if (side == 0) g_lcntT[b][grp] = base; else g_lcntS[b][grp] = base;
    }
}

// ---------------- feats f32 [b][orig n][c] -> fp16 [b][c][sorted n] ----------
__global__ void feats_transpose(const float* __restrict__ f) {
    __shared__ float tile[32][33];
    int b = blockIdx.z;
    int n0 = blockIdx.x * 32, c0 = blockIdx.y * 32;
    int tx = threadIdx.x, ty = threadIdx.y;
    #pragma unroll
    for (int j = 0; j < 4; j++) {
        int n = n0 + ty + j * 8;
        int on = g_sperm[b][n];
        tile[ty + j * 8][tx] = f[((b * Nn + on) * Cc) + (c0 + tx)];
    }
    __syncthreads();
    #pragma unroll
    for (int j = 0; j < 4; j++) {
        int c = c0 + ty + j * 8;
        g_fT[b][c][n0 + tx] = __float2half(tile[tx][ty + j * 8]);
    }
}

// ---------------- streaming LSE: list-driven, prefetched ----------------------
// block 256 = 8 warps x 4 rows = 32 rows; grid (4096/32, Bz)
template <int MODE>
__global__ __launch_bounds__(256) void lse_kernel(int iter) {
    const int b = blockIdx.y;
    const int warp = threadIdx.x >> 5, lane = threadIdx.x & 31;
    const int grp = blockIdx.x * 8 + warp;
    const int row0 = grp * 4;
    const float NEG_INV = -1.0f / 0.01000001f;
    const unsigned FULL = 0xffffffffu;

    // list: 128 bytes -> 1 uint32 per lane; element i via shfl
    const unsigned lw = ((const unsigned*)((MODE == 0) ? g_lstT[b][grp] : g_lstS[b][grp]))[lane];
    const int cnt = (MODE == 0) ? g_lcntT[b][grp] : g_lcntS[b][grp];

    float tx[4], ty[4], mx[4], ss[4];
    #pragma unroll
    for (int r = 0; r < 4; r++) {
        float4 p = (MODE == 0) ? g_tu4[b][row0 + r] : g_sv4[b][row0 + r];
        tx[r] = p.x; ty[r] = p.y;
        mx[r] = -1e30f; ss[r] = 0.0f;
    }

    const float4* opp = (MODE == 0) ? g_sv4[b] : g_tu4[b];

    float4 q = make_float4(0.f, 0.f, 0.f, 0.f);
    if (cnt > 0) {
        unsigned w0 = __shfl_sync(FULL, lw, 0);
        q = opp[(int)(w0 & 255u) * 32 + lane];
    }

    for (int i = 0; i < cnt; i++) {
        float4 qn = q;
        if (i + 1 < cnt) {
            unsigned w = __shfl_sync(FULL, lw, (i + 1) >> 2);
            int idn = (int)((w >> (((i + 1) & 3) * 8)) & 255u);
            qn = opp[idn * 32 + lane];
        }
        #pragma unroll
        for (int r = 0; r < 4; r++) {
            float dx = __fadd_rn(tx[r], -q.x);
            float dy = __fadd_rn(ty[r], -q.y);
            float d2 = __fadd_rn(__fmul_rn(dx, dx), __fmul_rn(dy, dy));
            bool ok = (d2 < 0.04f);
            if (__any_sync(FULL, ok)) {
                if (ok) {
                    float x  = __fmaf_rn(d2, NEG_INV, q.z);
                    float dd = x - mx[r];
                    float e  = __expf(-fabsf(dd));
                    if (dd > 0.0f) { ss[r] = __fmaf_rn(ss[r], e, 1.0f); mx[r] = x; }
                    else           { ss[r] += e; }
                }
            }
        }
        q = qn;
    }

    #pragma unroll
    for (int off = 16; off; off >>= 1) {
        #pragma unroll
        for (int r = 0; r < 4; r++) {
            float m2 = __shfl_xor_sync(FULL, mx[r], off);
            float s2 = __shfl_xor_sync(FULL, ss[r], off);
            float M  = fmaxf(mx[r], m2);
            ss[r] = ss[r] * __expf(mx[r] - M) + s2 * __expf(m2 - M);
            mx[r] = M;
        }
    }

    #pragma unroll
    for (int r = 0; r < 4; r++) {
        if (lane == r) {
            float m = mx[r], s = ss[r];
            int row = row0 + r;
            if (MODE == 0) {
                bool anyvalid = (s > 0.0f);
                float dual = anyvalid ? -(m + __logf(s)) : 1.0e9f;
                if (!anyvalid) atomicAdd(&g_cnt0[iter * Bz + b], 1);
                g_tu4[b][row].z = dual;
                g_has[b][row] = anyvalid ? 1 : 0;
            } else {
                int cnt0 = g_cnt0[iter * Bz + b];
                if (cnt0 > 0) {
                    float M = fmaxf(m, 0.0f);
                    s = s * __expf(m - M) + (float)cnt0 * __expf(0.0f - M);
                    m = M;
                }
                float dual = (s == 0.0f) ? 1.0e9f : -(m + __logf(s));
                g_sv4[b][row].z = g_sok[b][row] ? dual : 0.0f;
            }
        }
    }
}

// ---------------- fused attn-recompute GEMM ----------------------------------
__device__ __forceinline__ void mma16816(float& c0, float& c1, float& c2, float& c3,
                                         unsigned a0, unsigned a1, unsigned a2, unsigned a3,
                                         unsigned b0, unsigned b1) {
    asm volatile(
        "mma.sync.aligned.m16n8k16.row.col.f32.f16.f16.f32 "
        "{%0,%1,%2,%3}, {%4,%5,%6,%7}, {%8,%9}, {%0,%1,%2,%3};\n"
        : "+f"(c0), "+f"(c1), "+f"(c2), "+f"(c3)
        : "r"(a0), "r"(a1), "r"(a2), "r"(a3), "r"(b0), "r"(b1));
}

__device__ __forceinline__ float attn_val(float txx, float tyy, float uu, float4 q) {
    const float NEG_INV = -1.0f / 0.01000001f;
    float dx = __fadd_rn(txx, -q.x);
    float dy = __fadd_rn(tyy, -q.y);
    float d2 = __fadd_rn(__fmul_rn(dx, dx), __fmul_rn(dy, dy));
    if (d2 < 0.04f)
        return __expf(__fadd_rn(__fmaf_rn(d2, NEG_INV, uu), q.z));
    return 0.0f;
}

__device__ __forceinline__ unsigned pack2(float x, float y) {
    __half2 h = __floats2half2_rn(x, y);
    return *reinterpret_cast<unsigned*>(&h);
}

#define GBM 64
#define GBC 128
#define GBK 64
#define SBSTRIDE 72

__global__ __launch_bounds__(128) void gemm_kernel(float* __restrict__ out) {
    const int b  = blockIdx.z;
    const int m0 = blockIdx.x * GBM;
    const int c0 = blockIdx.y * GBC;
    const int warp = threadIdx.x >> 5, lane = threadIdx.x & 31;
    const int gid = lane >> 2, tig = lane & 3;

    __shared__ __align__(16) __half sB[GBC][SBSTRIDE];
    __shared__ __align__(16) float4 sS[GBK];

    float tmnx, tmxx, tmny, tmxy;
    {
        float4 b0 = g_tbb[b][(m0 >> 5) + 0], b1 = g_tbb[b][(m0 >> 5) + 1];
        tmnx = fminf(b0.x, b1.x); tmny = fminf(b0.y, b1.y);
        tmxx = fmaxf(b0.z, b1.z); tmxy = fmaxf(b0.w, b1.w);
    }

    const int rlo = m0 + warp * 16 + gid;
    const int rhi = rlo + 8;
    const float4 plo = g_tu4[b][rlo];
    const float4 phi = g_tu4[b][rhi];
    const bool haslo = g_has[b][rlo] != 0;
    const bool hashi = g_has[b][rhi] != 0;

    float acc[16][4];
    #pragma unroll
    for (int j = 0; j < 16; j++) {
        acc[j][0] = 0.f; acc[j][1] = 0.f; acc[j][2] = 0.f; acc[j][3] = 0.f;
    }

    for (int n0 = 0; n0 < Nn; n0 += GBK) {
        {
            float4 s0 = g_sbb[b][(n0 >> 5) + 0], s1 = g_sbb[b][(n0 >> 5) + 1];
            float smnx = fminf(s0.x, s1.x), smny = fminf(s0.y, s1.y);
            float smxx = fmaxf(s0.z, s1.z), smxy = fmaxf(s0.w, s1.w);
            float ddx = fmaxf(fmaxf(smnx - tmxx, tmnx - smxx), 0.0f);
            float ddy = fmaxf(fmaxf(smny - tmxy, tmny - smxy), 0.0f);
            if (ddx * ddx + ddy * ddy >= 0.0401f) continue;
        }
        __syncthreads();
        {
            int idx = threadIdx.x;
            #pragma unroll
            for (int t = 0; t < 8; t++, idx += 128) {
                int row = idx >> 3, ch = idx & 7;
                const uint4* src = reinterpret_cast<const uint4*>(&g_fT[b][c0 + row][n0]) + ch;
                *reinterpret_cast<uint4*>(&sB[row][ch * 8]) = *src;
            }
        }
        if (threadIdx.x < GBK) sS[threadIdx.x] = g_sv4[b][n0 + threadIdx.x];
        __syncthreads();

        #pragma unroll
        for (int kf = 0; kf < 4; kf++) {
            const int kb = kf * 16 + 2 * tig;
            float4 qa = sS[kb];
            float4 qb = sS[kb + 1];
            float4 qc = sS[kb + 8];
            float4 qd = sS[kb + 9];

            unsigned a0 = pack2(attn_val(plo.x, plo.y, plo.z, qa), attn_val(plo.x, plo.y, plo.z, qb));
            unsigned a1 = pack2(attn_val(phi.x, phi.y, phi.z, qa), attn_val(phi.x, phi.y, phi.z, qb));
            unsigned a2 = pack2(attn_val(plo.x, plo.y, plo.z, qc), attn_val(plo.x, plo.y, plo.z, qd));
            unsigned a3 = pack2(attn_val(phi.x, phi.y, phi.z, qc), attn_val(phi.x, phi.y, phi.z, qd));

            #pragma unroll
            for (int j = 0; j < 16; j++) {
                const __half* brow = &sB[j * 8 + gid][kf * 16 + 2 * tig];
                unsigned b0 = *reinterpret_cast<const unsigned*>(brow);
                unsigned b1 = *reinterpret_cast<const unsigned*>(brow + 8);
                mma16816(acc[j][0], acc[j][1], acc[j][2], acc[j][3],
                         a0, a1, a2, a3, b0, b1);
            }
        }
    }

    const int orlo = g_tperm[b][rlo];
    const int orhi = g_tperm[b][rhi];
    #pragma unroll
    for (int j = 0; j < 16; j++) {
        int c = c0 + j * 8 + 2 * tig;
        float2 vlo = haslo ? make_float2(acc[j][0], acc[j][1]) : make_float2(0.f, 0.f);
        float2 vhi = hashi ? make_float2(acc[j][2], acc[j][3]) : make_float2(0.f, 0.f);
        *reinterpret_cast<float2*>(&out[((b * Mm + orlo) * Cc) + c]) = vlo;
        *reinterpret_cast<float2*>(&out[((b * Mm + orhi) * Cc) + c]) = vhi;
    }
}

// ------------------------------- launch ---------------------------------------
extern "C" void kernel_launch(void* const* d_in, const int* in_sizes, int n_in,
                              void* d_out, int out_size) {
    const float* feats = (const float*)d_in[0];
    const float* slocs = (const float*)d_in[1];
    const float* tlocs = (const float*)d_in[2];
    const void*  smask = d_in[3];
    const void*  tmask = d_in[4];
    float* out = (float*)d_out;

    prep_kernel<<<(Bz * Nn + 255) / 256, 256>>>(slocs, tlocs, smask, tmask);
    sort_kernel<<<dim3(2, Bz), 1024>>>();
    scatter_kernel<<<dim3(16, Bz, 2), 256>>>();
    build_lists<<<dim3(NGRP / 8, Bz, 2), 256>>>();
    feats_transpose<<<dim3(Nn / 32, Cc / 32, Bz), dim3(32, 8)>>>(feats);

    for (int it = 0; it < 3; it++) {
        lse_kernel<0><<<dim3(Mm / 32, Bz), 256>>>(it);
        lse_kernel<1><<<dim3(Nn / 32, Bz), 256>>>(it);
    }

    gemm_kernel<<<dim3(Mm / GBM, Cc / GBC, Bz), 128>>>(out);
}

// round 7
// speedup vs baseline: 1.3087x; 1.2270x over previous
#include <cuda_runtime.h>
#include <cuda_fp16.h>
#include <stdint.h>

#define Bz 4
#define Nn 4096
#define Mm 4096
#define Cc 256
#define NGRP (Mm / 4)

// ---------------- persistent device scratch (no runtime alloc) ----------------
__device__ __align__(16) float2 g_sl0[Bz][Nn];
__device__ __align__(16) float2 g_tl0[Bz][Mm];
__device__ unsigned char g_sok0[Bz][Nn];
__device__ int g_tkey[Bz][Mm];
__device__ int g_skey[Bz][Nn];
__device__ int g_tperm[Bz][Mm];
__device__ int g_sperm[Bz][Nn];

// SORTED packed arrays: (x, y, dual, 0)
__device__ __align__(16) float4 g_sv4[Bz][Nn];
__device__ __align__(16) float4 g_tu4[Bz][Mm];
__device__ unsigned char g_sok[Bz][Nn];
__device__ unsigned char g_has[Bz][Mm];
__device__ __align__(16) float4 g_sbb[Bz][Nn / 32];
__device__ __align__(16) float4 g_tbb[Bz][Mm / 32];
__device__ int g_cnt0[3 * Bz];
__device__ __align__(16) __half g_fT[Bz][Cc][Nn];

// chunk include-lists: per 4-row group, uint8 chunk ids (<=128)
__device__ __align__(16) unsigned char g_lstT[Bz][NGRP][128];
__device__ __align__(16) unsigned char g_lstS[Bz][NGRP][128];
__device__ int g_lcntT[Bz][NGRP];
__device__ int g_lcntS[Bz][NGRP];

// ---------------- mask dtype auto-detect ------------------------------------
__device__ __forceinline__ int detect_fmt(const unsigned* w) {
    bool sawF = false, sawU = false;
    for (int i = 0; i < 64; i++) {
        unsigned v = w[i];
        if (v == 0x3F800000u) sawF = true;
        else if (v > 1u) {
            unsigned b0 = v & 255u, b1 = (v >> 8) & 255u, b2 = (v >> 16) & 255u, b3 = v >> 24;
            if (b0 <= 1u && b1 <= 1u && b2 <= 1u && b3 <= 1u) sawU = true;
            else sawF = true;
        }
    }
    if (sawF) return 2;
    if (sawU) return 0;
    return 1;
}
__device__ __forceinline__ bool read_mask(const void* p, int i, int fmt) {
    if (fmt == 0) return ((const unsigned char*)p)[i] != 0;
    if (fmt == 1) return ((const int*)p)[i] != 0;
    return ((const float*)p)[i] != 0.0f;
}

__device__ __forceinline__ unsigned spread4(unsigned x) {
    x &= 15u; x = (x | (x << 2)) & 0x33u; x = (x | (x << 1)) & 0x55u; return x;
}
__device__ __forceinline__ int morton_key(float x, float y) {
    int cx = (int)(x * 16.0f); cx = cx < 0 ? 0 : (cx > 15 ? 15 : cx);
    int cy = (int)(y * 16.0f); cy = cy < 0 ? 0 : (cy > 15 ? 15 : cy);
    return (int)(spread4((unsigned)cx) | (spread4((unsigned)cy) << 1));
}

// ---------------- prep -------------------------------------------------------
__global__ void prep_kernel(const float* __restrict__ slocs,
                            const float* __restrict__ tlocs,
                            const void* __restrict__ smask,
                            const void* __restrict__ tmask) {
    __shared__ int sf[2];
    if (threadIdx.x == 0) {
        sf[0] = detect_fmt((const unsigned*)smask);
        sf[1] = detect_fmt((const unsigned*)tmask);
    }
    __syncthreads();
    int i = blockIdx.x * blockDim.x + threadIdx.x;
    if (blockIdx.x == 0 && threadIdx.x < 3 * Bz) g_cnt0[threadIdx.x] = 0;
    if (i >= Bz * Nn) return;
    int b = i / Nn, n = i % Nn;

    bool sok = read_mask(smask, i, sf[0]);
    float sx = slocs[2 * i], sy = slocs[2 * i + 1];
    g_sl0[b][n] = make_float2(sok ? sx : -1e18f, sy);
    g_sok0[b][n] = sok ? 1 : 0;
    g_skey[b][n] = sok ? morton_key(sx, sy) : 256;

    bool tok = read_mask(tmask, i, sf[1]);
    float tx = tlocs[2 * i], ty = tlocs[2 * i + 1];
    g_tl0[b][n] = make_float2(tok ? tx : 1e18f, ty);
    g_tkey[b][n] = tok ? morton_key(tx, ty) : 256;
}

// ---------------- fused bitonic sort + scatter + chunk bboxes -----------------
__global__ __launch_bounds__(1024) void sort_scatter_kernel() {
    __shared__ unsigned sk[4096];
    int side = blockIdx.x, b = blockIdx.y, tid = threadIdx.x;
    int lane = tid & 31;
    for (int i = tid; i < 4096; i += 1024) {
        int key = side ? g_skey[b][i] : g_tkey[b][i];
        sk[i] = ((unsigned)key << 12) | (unsigned)i;
    }
    __syncthreads();
    for (int k = 2; k <= 4096; k <<= 1) {
        for (int j = k >> 1; j >= 1; j >>= 1) {
            for (int i = tid; i < 4096; i += 1024) {
                int l = i ^ j;
                if (l > i) {
                    unsigned a = sk[i], c = sk[l];
                    bool up = ((i & k) == 0);
                    if ((a > c) == up) { sk[i] = c; sk[l] = a; }
                }
            }
            __syncthreads();
        }
    }
    // scatter + per-32-chunk bbox (lanes cover 32 consecutive i)
    for (int i = tid; i < 4096; i += 1024) {
        int idx = (int)(sk[i] & 0xFFFu);
        float2 p;
        if (side) {
            p = g_sl0[b][idx];
            g_sv4[b][i] = make_float4(p.x, p.y, 0.0f, 0.0f);
            g_sok[b][i] = g_sok0[b][idx];
            g_sperm[b][i] = idx;
        } else {
            p = g_tl0[b][idx];
            g_tu4[b][i] = make_float4(p.x, p.y, 0.0f, 0.0f);
            g_tperm[b][i] = idx;
        }
        float mnx = p.x, mxx = p.x, mny = p.y, mxy = p.y;
        #pragma unroll
        for (int off = 16; off; off >>= 1) {
            mnx = fminf(mnx, __shfl_xor_sync(0xffffffffu, mnx, off));
            mxx = fmaxf(mxx, __shfl_xor_sync(0xffffffffu, mxx, off));
            mny = fminf(mny, __shfl_xor_sync(0xffffffffu, mny, off));
            mxy = fmaxf(mxy, __shfl_xor_sync(0xffffffffu, mxy, off));
        }
        if (lane == 0) {
            int chunk = i >> 5;
            float4 bb = make_float4(mnx, mny, mxx, mxy);
            if (side) g_sbb[b][chunk] = bb; else g_tbb[b][chunk] = bb;
        }
    }
}

// ---------------- build per-group chunk include-lists ------------------------
__global__ __launch_bounds__(256) void build_lists() {
    int b = blockIdx.y, side = blockIdx.z;
    int warp = threadIdx.x >> 5, lane = threadIdx.x & 31;
    int grp = blockIdx.x * 8 + warp;
    int row0 = grp * 4;

    float rmnx = 1e30f, rmxx = -1e30f, rmny = 1e30f, rmxy = -1e30f;
    #pragma unroll
    for (int r = 0; r < 4; r++) {
        float4 p = (side == 0) ? g_tu4[b][row0 + r] : g_sv4[b][row0 + r];
        rmnx = fminf(rmnx, p.x); rmxx = fmaxf(rmxx, p.x);
        rmny = fminf(rmny, p.y); rmxy = fmaxf(rmxy, p.y);
    }

    unsigned char* lst = (side == 0) ? g_lstT[b][grp] : g_lstS[b][grp];
    int base = 0;
    #pragma unroll
    for (int t = 0; t < 4; t++) {
        int c = t * 32 + lane;
        float4 cb = (side == 0) ? g_sbb[b][c] : g_tbb[b][c];
        float ddx = fmaxf(fmaxf(cb.x - rmxx, rmnx - cb.z), 0.0f);
        float ddy = fmaxf(fmaxf(cb.y - rmxy, rmny - cb.w), 0.0f);
        bool inc = (ddx * ddx + ddy * ddy < 0.0401f);
        unsigned mask = __ballot_sync(0xffffffffu, inc);
        if (inc) lst[base + __popc(mask & ((1u << lane) - 1u))] = (unsigned char)c;
        base += __popc(mask);
    }
    if (lane == 0) {
        if (side == 0) g_lcntT[b][grp] = base; else g_lcntS[b][grp] = base;
    }
}

// ---------------- feats f32 [b][orig n][c] -> fp16 [b][c][sorted n] ----------
__global__ void feats_transpose(const float* __restrict__ f) {
    __shared__ float tile[32][33];
    int b = blockIdx.z;
    int n0 = blockIdx.x * 32, c0 = blockIdx.y * 32;
    int tx = threadIdx.x, ty = threadIdx.y;
    #pragma unroll
    for (int j = 0; j < 4; j++) {
        int n = n0 + ty + j * 8;
        int on = g_sperm[b][n];
        tile[ty + j * 8][tx] = f[((b * Nn + on) * Cc) + (c0 + tx)];
    }
    __syncthreads();
    #pragma unroll
    for (int j = 0; j < 4; j++) {
        int c = c0 + ty + j * 8;
        g_fT[b][c][n0 + tx] = __float2half(tile[tx][ty + j * 8]);
    }
}

// ---------------- streaming LSE: list-driven, prefetched, log2-domain --------
// block 256 = 8 warps x 4 rows; grid (128, Bz); warp w of block x -> grp x + w*128
template <int MODE>
__global__ __launch_bounds__(256) void lse_kernel(int iter) {
    const int b = blockIdx.y;
    const int warp = threadIdx.x >> 5, lane = threadIdx.x & 31;
    const int grp = blockIdx.x + warp * 128;       // stride interleave: balance blocks
    const int row0 = grp * 4;
    const float L2E = 1.4426950408889634f;
    const float NEG_INV2 = (-1.0f / 0.01000001f) * 1.4426950408889634f;
    const float LN2 = 0.6931471805599453f;
    const unsigned FULL = 0xffffffffu;

    const unsigned lw = ((const unsigned*)((MODE == 0) ? g_lstT[b][grp] : g_lstS[b][grp]))[lane];
    const int cnt = (MODE == 0) ? g_lcntT[b][grp] : g_lcntS[b][grp];

    float tx[4], ty[4], mx[4], ss[4];
    #pragma unroll
    for (int r = 0; r < 4; r++) {
        float4 p = (MODE == 0) ? g_tu4[b][row0 + r] : g_sv4[b][row0 + r];
        tx[r] = p.x; ty[r] = p.y;
        mx[r] = -1e30f; ss[r] = 0.0f;
    }

    const float4* opp = (MODE == 0) ? g_sv4[b] : g_tu4[b];

    float4 q = make_float4(0.f, 0.f, 0.f, 0.f);
    if (cnt > 0) {
        unsigned w0 = __shfl_sync(FULL, lw, 0);
        q = opp[(int)(w0 & 255u) * 32 + lane];
    }

    for (int i = 0; i < cnt; i++) {
        float4 qn = q;
        if (i + 1 < cnt) {
            unsigned w = __shfl_sync(FULL, lw, (i + 1) >> 2);
            int idn = (int)((w >> (((i + 1) & 3) * 8)) & 255u);
            qn = opp[idn * 32 + lane];
        }
        float z2 = q.z * L2E;                     // log2-domain dual (1 mul / 4 rows)
        #pragma unroll
        for (int r = 0; r < 4; r++) {
            float dx = __fadd_rn(tx[r], -q.x);
            float dy = __fadd_rn(ty[r], -q.y);
            float d2 = __fadd_rn(__fmul_rn(dx, dx), __fmul_rn(dy, dy));
            if (d2 < 0.04f) {
                float x  = __fmaf_rn(d2, NEG_INV2, z2);
                float dd = x - mx[r];
                float e  = exp2f(-fabsf(dd));
                if (dd > 0.0f) { ss[r] = __fmaf_rn(ss[r], e, 1.0f); mx[r] = x; }
                else           { ss[r] += e; }
            }
        }
        q = qn;
    }

    #pragma unroll
    for (int off = 16; off; off >>= 1) {
        #pragma unroll
        for (int r = 0; r < 4; r++) {
            float m2 = __shfl_xor_sync(FULL, mx[r], off);
            float s2 = __shfl_xor_sync(FULL, ss[r], off);
            float M  = fmaxf(mx[r], m2);
            ss[r] = ss[r] * exp2f(mx[r] - M) + s2 * exp2f(m2 - M);
            mx[r] = M;
        }
    }

    #pragma unroll
    for (int r = 0; r < 4; r++) {
        if (lane == r) {
            float m = mx[r], s = ss[r];
            int row = row0 + r;
            if (MODE == 0) {
                bool anyvalid = (s > 0.0f);
                float dual = anyvalid ? -LN2 * (m + log2f(s)) : 1.0e9f;
                if (!anyvalid) atomicAdd(&g_cnt0[iter * Bz + b], 1);
                g_tu4[b][row].z = dual;
                g_has[b][row] = anyvalid ? 1 : 0;
            } else {
                int cnt0 = g_cnt0[iter * Bz + b];
                if (cnt0 > 0) {
                    float M = fmaxf(m, 0.0f);
                    s = s * exp2f(m - M) + (float)cnt0 * exp2f(0.0f - M);
                    m = M;
                }
                float dual = (s == 0.0f) ? 1.0e9f : -LN2 * (m + log2f(s));
                g_sv4[b][row].z = g_sok[b][row] ? dual : 0.0f;
            }
        }
    }
}

// ---------------- fused attn-recompute GEMM ----------------------------------
__device__ __forceinline__ void mma16816(float& c0, float& c1, float& c2, float& c3,
                                         unsigned a0, unsigned a1, unsigned a2, unsigned a3,
                                         unsigned b0, unsigned b1) {
    asm volatile(
        "mma.sync.aligned.m16n8k16.row.col.f32.f16.f16.f32 "
        "{%0,%1,%2,%3}, {%4,%5,%6,%7}, {%8,%9}, {%0,%1,%2,%3};\n"
        : "+f"(c0), "+f"(c1), "+f"(c2), "+f"(c3)
        : "r"(a0), "r"(a1), "r"(a2), "r"(a3), "r"(b0), "r"(b1));
}

__device__ __forceinline__ float attn_val(float txx, float tyy, float uu, float4 q) {
    const float NEG_INV = -1.0f / 0.01000001f;
    float dx = __fadd_rn(txx, -q.x);
    float dy = __fadd_rn(tyy, -q.y);
    float d2 = __fadd_rn(__fmul_rn(dx, dx), __fmul_rn(dy, dy));
    if (d2 < 0.04f)
        return __expf(__fadd_rn(__fmaf_rn(d2, NEG_INV, uu), q.z));
    return 0.0f;
}

__device__ __forceinline__ unsigned pack2(float x, float y) {
    __half2 h = __floats2half2_rn(x, y);
    return *reinterpret_cast<unsigned*>(&h);
}

#define GBM 64
#define GBC 128
#define GBK 64
#define SBSTRIDE 72

__global__ __launch_bounds__(128) void gemm_kernel(float* __restrict__ out) {
    const int b  = blockIdx.z;
    const int m0 = blockIdx.x * GBM;
    const int c0 = blockIdx.y * GBC;
    const int warp = threadIdx.x >> 5, lane = threadIdx.x & 31;
    const int gid = lane >> 2, tig = lane & 3;

    __shared__ __align__(16) __half sB[GBC][SBSTRIDE];
    __shared__ __align__(16) float4 sS[GBK];

    float tmnx, tmxx, tmny, tmxy;
    {
        float4 b0 = g_tbb[b][(m0 >> 5) + 0], b1 = g_tbb[b][(m0 >> 5) + 1];
        tmnx = fminf(b0.x, b1.x); tmny = fminf(b0.y, b1.y);
        tmxx = fmaxf(b0.z, b1.z); tmxy = fmaxf(b0.w, b1.w);
    }

    const int rlo = m0 + warp * 16 + gid;
    const int rhi = rlo + 8;
    const float4 plo = g_tu4[b][rlo];
    const float4 phi = g_tu4[b][rhi];
    const bool haslo = g_has[b][rlo] != 0;
    const bool hashi = g_has[b][rhi] != 0;

    float acc[16][4];
    #pragma unroll
    for (int j = 0; j < 16; j++) {
        acc[j][0] = 0.f; acc[j][1] = 0.f; acc[j][2] = 0.f; acc[j][3] = 0.f;
    }

    for (int n0 = 0; n0 < Nn; n0 += GBK) {
        {
            float4 s0 = g_sbb[b][(n0 >> 5) + 0], s1 = g_sbb[b][(n0 >> 5) + 1];
            float smnx = fminf(s0.x, s1.x), smny = fminf(s0.y, s1.y);
            float smxx = fmaxf(s0.z, s1.z), smxy = fmaxf(s0.w, s1.w);
            float ddx = fmaxf(fmaxf(smnx - tmxx, tmnx - smxx), 0.0f);
            float ddy = fmaxf(fmaxf(smny - tmxy, tmny - smxy), 0.0f);
            if (ddx * ddx + ddy * ddy >= 0.0401f) continue;
        }
        __syncthreads();
        {
            int idx = threadIdx.x;
            #pragma unroll
            for (int t = 0; t < 8; t++, idx += 128) {
                int row = idx >> 3, ch = idx & 7;
                const uint4* src = reinterpret_cast<const uint4*>(&g_fT[b][c0 + row][n0]) + ch;
                *reinterpret_cast<uint4*>(&sB[row][ch * 8]) = *src;
            }
        }
        if (threadIdx.x < GBK) sS[threadIdx.x] = g_sv4[b][n0 + threadIdx.x];
        __syncthreads();

        #pragma unroll
        for (int kf = 0; kf < 4; kf++) {
            const int kb = kf * 16 + 2 * tig;
            float4 qa = sS[kb];
            float4 qb = sS[kb + 1];
            float4 qc = sS[kb + 8];
            float4 qd = sS[kb + 9];

            unsigned a0 = pack2(attn_val(plo.x, plo.y, plo.z, qa), attn_val(plo.x, plo.y, plo.z, qb));
            unsigned a1 = pack2(attn_val(phi.x, phi.y, phi.z, qa), attn_val(phi.x, phi.y, phi.z, qb));
            unsigned a2 = pack2(attn_val(plo.x, plo.y, plo.z, qc), attn_val(plo.x, plo.y, plo.z, qd));
            unsigned a3 = pack2(attn_val(phi.x, phi.y, phi.z, qc), attn_val(phi.x, phi.y, phi.z, qd));

            #pragma unroll
            for (int j = 0; j < 16; j++) {
                const __half* brow = &sB[j * 8 + gid][kf * 16 + 2 * tig];
                unsigned b0 = *reinterpret_cast<const unsigned*>(brow);
                unsigned b1 = *reinterpret_cast<const unsigned*>(brow + 8);
                mma16816(acc[j][0], acc[j][1], acc[j][2], acc[j][3],
                         a0, a1, a2, a3, b0, b1);
            }
        }
    }

    const int orlo = g_tperm[b][rlo];
    const int orhi = g_tperm[b][rhi];
    #pragma unroll
    for (int j = 0; j < 16; j++) {
        int c = c0 + j * 8 + 2 * tig;
        float2 vlo = haslo ? make_float2(acc[j][0], acc[j][1]) : make_float2(0.f, 0.f);
        float2 vhi = hashi ? make_float2(acc[j][2], acc[j][3]) : make_float2(0.f, 0.f);
        *reinterpret_cast<float2*>(&out[((b * Mm + orlo) * Cc) + c]) = vlo;
        *reinterpret_cast<float2*>(&out[((b * Mm + orhi) * Cc) + c]) = vhi;
    }
}

// ------------------------------- launch ---------------------------------------
extern "C" void kernel_launch(void* const* d_in, const int* in_sizes, int n_in,
                              void* d_out, int out_size) {
    const float* feats = (const float*)d_in[0];
    const float* slocs = (const float*)d_in[1];
    const float* tlocs = (const float*)d_in[2];
    const void*  smask = d_in[3];
    const void*  tmask = d_in[4];
    float* out = (float*)d_out;

    prep_kernel<<<(Bz * Nn + 255) / 256, 256>>>(slocs, tlocs, smask, tmask);       // 1
    sort_scatter_kernel<<<dim3(2, Bz), 1024>>>();                                   // 2
    build_lists<<<dim3(NGRP / 8, Bz, 2), 256>>>();                                  // 3

    for (int it = 0; it < 3; it++) {
        lse_kernel<0><<<dim3(128, Bz), 256>>>(it);                                  // 4 <- profiled slot
        lse_kernel<1><<<dim3(128, Bz), 256>>>(it);
    }

    feats_transpose<<<dim3(Nn / 32, Cc / 32, Bz), dim3(32, 8)>>>(feats);
    gemm_kernel<<<dim3(Mm / GBM, Cc / GBC, Bz), 128>>>(out);
}

// round 8
// speedup vs baseline: 1.3709x; 1.0475x over previous
#include <cuda_runtime.h>
#include <cuda_fp16.h>
#include <stdint.h>

#define Bz 4
#define Nn 4096
#define Mm 4096
#define Cc 256
#define RSTRIDE 768

#define L2E  1.4426950408889634f
#define LN2  0.6931471805599453f
#define BIG2 1.0e9f
// (-1/(EPSILON+1e-8)) * log2(e), computed in double then rounded once
__device__ __constant__ float c_NEG_INV2 = (float)(-1.0 / 0.01000001 * 1.4426950408889634);

// ---------------- persistent device scratch (no runtime alloc) ----------------
__device__ __align__(16) float2 g_sl0[Bz][Nn];
__device__ __align__(16) float2 g_tl0[Bz][Mm];
__device__ unsigned char g_sok0[Bz][Nn];
__device__ int g_tkey[Bz][Mm];
__device__ int g_skey[Bz][Nn];
__device__ int g_tperm[Bz][Mm];
__device__ int g_sperm[Bz][Nn];

// SORTED coords (z,w unused in math; z refilled at GEMM staging)
__device__ __align__(16) float4 g_sv4[Bz][Nn];
__device__ __align__(16) float4 g_tu4[Bz][Mm];
__device__ unsigned char g_sok[Bz][Nn];
__device__ unsigned char g_has[Bz][Mm];
__device__ __align__(16) float4 g_sbb[Bz][Nn / 32];
__device__ __align__(16) float4 g_tbb[Bz][Mm / 32];

// duals in log2 domain
__device__ float g_u2[Bz][Mm];
__device__ float g_v2[Bz][Nn];
__device__ int g_cnt0u[3 * Bz];
__device__ int g_cnt0v[3 * Bz];

// padded CSR: entry = {col, f32bits(lk2)}
__device__ uint2 g_csrT[Bz][Mm * RSTRIDE];   // target rows <- source cols (u-pass)
__device__ uint2 g_csrS[Bz][Nn * RSTRIDE];   // source rows <- target cols (v-pass)
__device__ int g_nnzT[Bz][Mm];
__device__ int g_nnzS[Bz][Nn];

__device__ __align__(16) __half g_fT[Bz][Cc][Nn];

// ---------------- mask dtype auto-detect ------------------------------------
__device__ __forceinline__ int detect_fmt(const unsigned* w) {
    bool sawF = false, sawU = false;
    for (int i = 0; i < 64; i++) {
        unsigned v = w[i];
        if (v == 0x3F800000u) sawF = true;
        else if (v > 1u) {
            unsigned b0 = v & 255u, b1 = (v >> 8) & 255u, b2 = (v >> 16) & 255u, b3 = v >> 24;
            if (b0 <= 1u && b1 <= 1u && b2 <= 1u && b3 <= 1u) sawU = true;
            else sawF = true;
        }
    }
    if (sawF) return 2;
    if (sawU) return 0;
    return 1;
}
__device__ __forceinline__ bool read_mask(const void* p, int i, int fmt) {
    if (fmt == 0) return ((const unsigned char*)p)[i] != 0;
    if (fmt == 1) return ((const int*)p)[i] != 0;
    return ((const float*)p)[i] != 0.0f;
}

__device__ __forceinline__ unsigned spread4(unsigned x) {
    x &= 15u; x = (x | (x << 2)) & 0x33u; x = (x | (x << 1)) & 0x55u; return x;
}
__device__ __forceinline__ int morton_key(float x, float y) {
    int cx = (int)(x * 16.0f); cx = cx < 0 ? 0 : (cx > 15 ? 15 : cx);
    int cy = (int)(y * 16.0f); cy = cy < 0 ? 0 : (cy > 15 ? 15 : cy);
    return (int)(spread4((unsigned)cx) | (spread4((unsigned)cy) << 1));
}

// ---------------- prep -------------------------------------------------------
__global__ void prep_kernel(const float* __restrict__ slocs,
                            const float* __restrict__ tlocs,
                            const void* __restrict__ smask,
                            const void* __restrict__ tmask) {
    __shared__ int sf[2];
    if (threadIdx.x == 0) {
        sf[0] = detect_fmt((const unsigned*)smask);
        sf[1] = detect_fmt((const unsigned*)tmask);
    }
    __syncthreads();
    int i = blockIdx.x * blockDim.x + threadIdx.x;
    if (blockIdx.x == 0 && threadIdx.x < 3 * Bz) {
        g_cnt0u[threadIdx.x] = 0;
        g_cnt0v[threadIdx.x] = 0;
    }
    if (i >= Bz * Nn) return;
    int b = i / Nn, n = i % Nn;

    bool sok = read_mask(smask, i, sf[0]);
    float sx = slocs[2 * i], sy = slocs[2 * i + 1];
    g_sl0[b][n] = make_float2(sok ? sx : -1e18f, sy);
    g_sok0[b][n] = sok ? 1 : 0;
    g_skey[b][n] = sok ? morton_key(sx, sy) : 256;
    g_v2[b][n] = 0.0f;

    bool tok = read_mask(tmask, i, sf[1]);
    float tx = tlocs[2 * i], ty = tlocs[2 * i + 1];
    g_tl0[b][n] = make_float2(tok ? tx : 1e18f, ty);
    g_tkey[b][n] = tok ? morton_key(tx, ty) : 256;
}

// ---------------- fused bitonic sort + scatter + chunk bboxes -----------------
__global__ __launch_bounds__(1024) void sort_scatter_kernel() {
    __shared__ unsigned sk[4096];
    int side = blockIdx.x, b = blockIdx.y, tid = threadIdx.x;
    int lane = tid & 31;
    for (int i = tid; i < 4096; i += 1024) {
        int key = side ? g_skey[b][i] : g_tkey[b][i];
        sk[i] = ((unsigned)key << 12) | (unsigned)i;
    }
    __syncthreads();
    for (int k = 2; k <= 4096; k <<= 1) {
        for (int j = k >> 1; j >= 1; j >>= 1) {
            for (int i = tid; i < 4096; i += 1024) {
                int l = i ^ j;
                if (l > i) {
                    unsigned a = sk[i], c = sk[l];
                    bool up = ((i & k) == 0);
                    if ((a > c) == up) { sk[i] = c; sk[l] = a; }
                }
            }
            __syncthreads();
        }
    }
    for (int i = tid; i < 4096; i += 1024) {
        int idx = (int)(sk[i] & 0xFFFu);
        float2 p;
        if (side) {
            p = g_sl0[b][idx];
            g_sv4[b][i] = make_float4(p.x, p.y, 0.0f, 0.0f);
            g_sok[b][i] = g_sok0[b][idx];
            g_sperm[b][i] = idx;
        } else {
            p = g_tl0[b][idx];
            g_tu4[b][i] = make_float4(p.x, p.y, 0.0f, 0.0f);
            g_tperm[b][i] = idx;
        }
        float mnx = p.x, mxx = p.x, mny = p.y, mxy = p.y;
        #pragma unroll
        for (int off = 16; off; off >>= 1) {
            mnx = fminf(mnx, __shfl_xor_sync(0xffffffffu, mnx, off));
            mxx = fmaxf(mxx, __shfl_xor_sync(0xffffffffu, mxx, off));
            mny = fminf(mny, __shfl_xor_sync(0xffffffffu, mny, off));
            mxy = fmaxf(mxy, __shfl_xor_sync(0xffffffffu, mxy, off));
        }
        if (lane == 0) {
            int chunk = i >> 5;
            float4 bb = make_float4(mnx, mny, mxx, mxy);
            if (side) g_sbb[b][chunk] = bb; else g_tbb[b][chunk] = bb;
        }
    }
}

// ---------------- build padded CSR (pairs + lk2) once -------------------------
// grid (4096/8, Bz, 2); block 256 = 8 warps; warp = one row
__global__ __launch_bounds__(256) void csr_build() {
    const int b = blockIdx.y, side = blockIdx.z;
    const int warp = threadIdx.x >> 5, lane = threadIdx.x & 31;
    const int row = blockIdx.x * 8 + warp;
    const unsigned FULL = 0xffffffffu;
    const float NEG_INV2 = c_NEG_INV2;

    float4 rp = (side == 0) ? g_tu4[b][row] : g_sv4[b][row];
    const float4* opp = (side == 0) ? g_sv4[b] : g_tu4[b];
    const float4* bb  = (side == 0) ? g_sbb[b] : g_tbb[b];
    uint2* seg = ((side == 0) ? g_csrT[b] : g_csrS[b]) + (size_t)row * RSTRIDE;

    int cnt = 0;
    #pragma unroll
    for (int t = 0; t < 4; t++) {
        int c = t * 32 + lane;
        float4 cb = bb[c];
        float ddx = fmaxf(fmaxf(cb.x - rp.x, rp.x - cb.z), 0.0f);
        float ddy = fmaxf(fmaxf(cb.y - rp.y, rp.y - cb.w), 0.0f);
        bool inc = (ddx * ddx + ddy * ddy < 0.0401f);
        unsigned mask = __ballot_sync(FULL, inc);
        while (mask) {
            int chunk = t * 32 + (__ffs(mask) - 1);
            mask &= mask - 1;
            int col = chunk * 32 + lane;
            float4 q = opp[col];
            float dx = __fadd_rn(rp.x, -q.x);
            float dy = __fadd_rn(rp.y, -q.y);
            float d2 = __fadd_rn(__fmul_rn(dx, dx), __fmul_rn(dy, dy));
            bool valid = (d2 < 0.04f);
            unsigned vm = __ballot_sync(FULL, valid);
            if (valid) {
                int slot = cnt + __popc(vm & ((1u << lane) - 1u));
                if (slot < RSTRIDE)
                    seg[slot] = make_uint2((unsigned)col,
                                           __float_as_uint(__fmul_rn(d2, NEG_INV2)));
            }
            cnt += __popc(vm);
        }
    }
    if (lane == 0) {
        cnt = cnt > RSTRIDE ? RSTRIDE : cnt;
        if (side == 0) { g_nnzT[b][row] = cnt; g_has[b][row] = (cnt > 0) ? 1 : 0; }
        else           { g_nnzS[b][row] = cnt; }
    }
}

// ---------------- LSE pass over CSR: no-max raw exp2 sum ----------------------
// grid (4096/8, Bz); block 256 = 8 warps; warp = row
template <int MODE>
__global__ __launch_bounds__(256) void lse_kernel(int iter) {
    const int b = blockIdx.y;
    const int warp = threadIdx.x >> 5, lane = threadIdx.x & 31;
    const int row = blockIdx.x * 8 + warp;
    const unsigned FULL = 0xffffffffu;

    const uint2* seg = ((MODE == 0) ? g_csrT[b] : g_csrS[b]) + (size_t)row * RSTRIDE;
    const float* dual = (MODE == 0) ? g_v2[b] : g_u2[b];
    const int cnt = (MODE == 0) ? g_nnzT[b][row] : g_nnzS[b][row];

    float s0 = 0.0f, s1 = 0.0f;
    int i = lane;
    for (; i + 32 < cnt; i += 64) {
        uint2 e0 = seg[i];
        uint2 e1 = seg[i + 32];
        s0 += exp2f(__uint_as_float(e0.y) + dual[e0.x]);
        s1 += exp2f(__uint_as_float(e1.y) + dual[e1.x]);
    }
    if (i < cnt) {
        uint2 e0 = seg[i];
        s0 += exp2f(__uint_as_float(e0.y) + dual[e0.x]);
    }
    float s = s0 + s1;
    #pragma unroll
    for (int off = 16; off; off >>= 1) s += __shfl_xor_sync(FULL, s, off);

    if (lane == 0) {
        if (MODE == 0) {
            float tot = s + ((iter > 0) ? (float)g_cnt0v[(iter - 1) * Bz + b] : 0.0f);
            float u2;
            if (tot > 0.0f) u2 = -log2f(tot);
            else { u2 = BIG2; atomicAdd(&g_cnt0u[iter * Bz + b], 1); }
            g_u2[b][row] = u2;
        } else {
            float tot = s + (float)g_cnt0u[iter * Bz + b];
            bool sok = g_sok[b][row] != 0;
            float v2;
            if (tot > 0.0f) v2 = -log2f(tot);
            else { v2 = BIG2; if (sok) atomicAdd(&g_cnt0v[iter * Bz + b], 1); }
            g_v2[b][row] = sok ? v2 : 0.0f;
        }
    }
}

// ---------------- feats f32 [b][orig n][c] -> fp16 [b][c][sorted n] ----------
__global__ void feats_transpose(const float* __restrict__ f) {
    __shared__ float tile[32][33];
    int b = blockIdx.z;
    int n0 = blockIdx.x * 32, c0 = blockIdx.y * 32;
    int tx = threadIdx.x, ty = threadIdx.y;
    #pragma unroll
    for (int j = 0; j < 4; j++) {
        int n = n0 + ty + j * 8;
        int on = g_sperm[b][n];
        tile[ty + j * 8][tx] = f[((b * Nn + on) * Cc) + (c0 + tx)];
    }
    __syncthreads();
    #pragma unroll
    for (int j = 0; j < 4; j++) {
        int c = c0 + ty + j * 8;
        g_fT[b][c][n0 + tx] = __float2half(tile[tx][ty + j * 8]);
    }
}

// ---------------- fused attn-recompute GEMM (log2-domain duals) --------------
__device__ __forceinline__ void mma16816(float& c0, float& c1, float& c2, float& c3,
                                         unsigned a0, unsigned a1, unsigned a2, unsigned a3,
                                         unsigned b0, unsigned b1) {
    asm volatile(
        "mma.sync.aligned.m16n8k16.row.col.f32.f16.f16.f32 "
        "{%0,%1,%2,%3}, {%4,%5,%6,%7}, {%8,%9}, {%0,%1,%2,%3};\n"
        : "+f"(c0), "+f"(c1), "+f"(c2), "+f"(c3)
        : "r"(a0), "r"(a1), "r"(a2), "r"(a3), "r"(b0), "r"(b1));
}

__device__ __forceinline__ float attn_val(float txx, float tyy, float uu2, float4 q) {
    float dx = __fadd_rn(txx, -q.x);
    float dy = __fadd_rn(tyy, -q.y);
    float d2 = __fadd_rn(__fmul_rn(dx, dx), __fmul_rn(dy, dy));
    if (d2 < 0.04f)
        return exp2f(__fadd_rn(__fmaf_rn(d2, c_NEG_INV2, uu2), q.z));
    return 0.0f;
}

__device__ __forceinline__ unsigned pack2(float x, float y) {
    __half2 h = __floats2half2_rn(x, y);
    return *reinterpret_cast<unsigned*>(&h);
}

#define GBM 64
#define GBC 128
#define GBK 64
#define SBSTRIDE 72

__global__ __launch_bounds__(128) void gemm_kernel(float* __restrict__ out) {
    const int b  = blockIdx.z;
    const int m0 = blockIdx.x * GBM;
    const int c0 = blockIdx.y * GBC;
    const int warp = threadIdx.x >> 5, lane = threadIdx.x & 31;
    const int gid = lane >> 2, tig = lane & 3;

    __shared__ __align__(16) __half sB[GBC][SBSTRIDE];
    __shared__ __align__(16) float4 sS[GBK];

    float tmnx, tmxx, tmny, tmxy;
    {
        float4 b0 = g_tbb[b][(m0 >> 5) + 0], b1 = g_tbb[b][(m0 >> 5) + 1];
        tmnx = fminf(b0.x, b1.x); tmny = fminf(b0.y, b1.y);
        tmxx = fmaxf(b0.z, b1.z); tmxy = fmaxf(b0.w, b1.w);
    }

    const int rlo = m0 + warp * 16 + gid;
    const int rhi = rlo + 8;
    float4 plo = g_tu4[b][rlo]; plo.z = g_u2[b][rlo];
    float4 phi = g_tu4[b][rhi]; phi.z = g_u2[b][rhi];
    const bool haslo = g_has[b][rlo] != 0;
    const bool hashi = g_has[b][rhi] != 0;

    float acc[16][4];
    #pragma unroll
    for (int j = 0; j < 16; j++) {
        acc[j][0] = 0.f; acc[j][1] = 0.f; acc[j][2] = 0.f; acc[j][3] = 0.f;
    }

    for (int n0 = 0; n0 < Nn; n0 += GBK) {
        {
            float4 s0 = g_sbb[b][(n0 >> 5) + 0], s1 = g_sbb[b][(n0 >> 5) + 1];
            float smnx = fminf(s0.x, s1.x), smny = fminf(s0.y, s1.y);
            float smxx = fmaxf(s0.z, s1.z), smxy = fmaxf(s0.w, s1.w);
            float ddx = fmaxf(fmaxf(smnx - tmxx, tmnx - smxx), 0.0f);
            float ddy = fmaxf(fmaxf(smny - tmxy, tmny - smxy), 0.0f);
            if (ddx * ddx + ddy * ddy >= 0.0401f) continue;
        }
        __syncthreads();
        {
            int idx = threadIdx.x;
            #pragma unroll
            for (int t = 0; t < 8; t++, idx += 128) {
                int row = idx >> 3, ch = idx & 7;
                const uint4* src = reinterpret_cast<const uint4*>(&g_fT[b][c0 + row][n0]) + ch;
                *reinterpret_cast<uint4*>(&sB[row][ch * 8]) = *src;
            }
        }
        if (threadIdx.x < GBK) {
            int n = n0 + threadIdx.x;
            float4 p = g_sv4[b][n];
            p.z = g_v2[b][n];
            sS[threadIdx.x] = p;
        }
        __syncthreads();

        #pragma unroll
        for (int kf = 0; kf < 4; kf++) {
            const int kb = kf * 16 + 2 * tig;
            float4 qa = sS[kb];
            float4 qb = sS[kb + 1];
            float4 qc = sS[kb + 8];
            float4 qd = sS[kb + 9];

            unsigned a0 = pack2(attn_val(plo.x, plo.y, plo.z, qa), attn_val(plo.x, plo.y, plo.z, qb));
            unsigned a1 = pack2(attn_val(phi.x, phi.y, phi.z, qa), attn_val(phi.x, phi.y, phi.z, qb));
            unsigned a2 = pack2(attn_val(plo.x, plo.y, plo.z, qc), attn_val(plo.x, plo.y, plo.z, qd));
            unsigned a3 = pack2(attn_val(phi.x, phi.y, phi.z, qc), attn_val(phi.x, phi.y, phi.z, qd));

            #pragma unroll
            for (int j = 0; j < 16; j++) {
                const __half* brow = &sB[j * 8 + gid][kf * 16 + 2 * tig];
                unsigned b0 = *reinterpret_cast<const unsigned*>(brow);
                unsigned b1 = *reinterpret_cast<const unsigned*>(brow + 8);
                mma16816(acc[j][0], acc[j][1], acc[j][2], acc[j][3],
                         a0, a1, a2, a3, b0, b1);
            }
        }
    }

    const int orlo = g_tperm[b][rlo];
    const int orhi = g_tperm[b][rhi];
    #pragma unroll
    for (int j = 0; j < 16; j++) {
        int c = c0 + j * 8 + 2 * tig;
        float2 vlo = haslo ? make_float2(acc[j][0], acc[j][1]) : make_float2(0.f, 0.f);
        float2 vhi = hashi ? make_float2(acc[j][2], acc[j][3]) : make_float2(0.f, 0.f);
        *reinterpret_cast<float2*>(&out[((b * Mm + orlo) * Cc) + c]) = vlo;
        *reinterpret_cast<float2*>(&out[((b * Mm + orhi) * Cc) + c]) = vhi;
    }
}

// ------------------------------- launch ---------------------------------------
extern "C" void kernel_launch(void* const* d_in, const int* in_sizes, int n_in,
                              void* d_out, int out_size) {
    const float* feats = (const float*)d_in[0];
    const float* slocs = (const float*)d_in[1];
    const float* tlocs = (const float*)d_in[2];
    const void*  smask = d_in[3];
    const void*  tmask = d_in[4];
    float* out = (float*)d_out;

    prep_kernel<<<(Bz * Nn + 255) / 256, 256>>>(slocs, tlocs, smask, tmask);   // 1
    sort_scatter_kernel<<<dim3(2, Bz), 1024>>>();                               // 2
    csr_build<<<dim3(4096 / 8, Bz, 2), 256>>>();                                // 3

    for (int it = 0; it < 3; it++) {
        lse_kernel<0><<<dim3(4096 / 8, Bz), 256>>>(it);                         // 4 <- profiled
        lse_kernel<1><<<dim3(4096 / 8, Bz), 256>>>(it);
    }

    feats_transpose<<<dim3(Nn / 32, Cc / 32, Bz), dim3(32, 8)>>>(feats);
    gemm_kernel<<<dim3(Mm / GBM, Cc / GBC, Bz), 128>>>(out);
}

// round 9
// speedup vs baseline: 1.4653x; 1.0689x over previous
#include <cuda_runtime.h>
#include <cuda_fp16.h>
#include <stdint.h>

#define Bz 4
#define Nn 4096
#define Mm 4096
#define Cc 256
#define RSTRIDE 768

#define BIG2 1.0e9f
// (-1/(EPSILON+1e-8)) * log2(e)
__device__ __constant__ float c_NEG_INV2 = (float)(-1.0 / 0.01000001 * 1.4426950408889634);

// ---------------- persistent device scratch (no runtime alloc) ----------------
__device__ __align__(16) float2 g_sl0[Bz][Nn];
__device__ __align__(16) float2 g_tl0[Bz][Mm];
__device__ unsigned char g_sok0[Bz][Nn];
__device__ int g_tkey[Bz][Mm];
__device__ int g_skey[Bz][Nn];
__device__ int g_tperm[Bz][Mm];
__device__ int g_sperm[Bz][Nn];

// SORTED coords
__device__ __align__(16) float4 g_sv4[Bz][Nn];
__device__ __align__(16) float4 g_tu4[Bz][Mm];
__device__ unsigned char g_sok[Bz][Nn];
__device__ unsigned char g_has[Bz][Mm];
__device__ __align__(16) float4 g_sbb[Bz][Nn / 32];
__device__ __align__(16) float4 g_tbb[Bz][Mm / 32];

// duals (log2 domain) + their exponentials
__device__ float g_u2[Bz][Mm];
__device__ float g_v2[Bz][Nn];
__device__ float g_eu[Bz][Mm];
__device__ float g_ev[Bz][Nn];
__device__ int g_cnt0u[3 * Bz];
__device__ int g_cnt0v[3 * Bz];

// padded CSR, SoA: col (u16) + K = exp2(lk2) (f32)
__device__ __align__(16) unsigned short g_colT[Bz][Mm * RSTRIDE];
__device__ __align__(16) unsigned short g_colS[Bz][Nn * RSTRIDE];
__device__ __align__(16) float g_valT[Bz][Mm * RSTRIDE];
__device__ __align__(16) float g_valS[Bz][Nn * RSTRIDE];
__device__ int g_nnzT[Bz][Mm];
__device__ int g_nnzS[Bz][Nn];

__device__ __align__(16) __half g_fT[Bz][Cc][Nn];

// ---------------- mask dtype auto-detect ------------------------------------
__device__ __forceinline__ int detect_fmt(const unsigned* w) {
    bool sawF = false, sawU = false;
    for (int i = 0; i < 64; i++) {
        unsigned v = w[i];
        if (v == 0x3F800000u) sawF = true;
        else if (v > 1u) {
            unsigned b0 = v & 255u, b1 = (v >> 8) & 255u, b2 = (v >> 16) & 255u, b3 = v >> 24;
            if (b0 <= 1u && b1 <= 1u && b2 <= 1u && b3 <= 1u) sawU = true;
            else sawF = true;
        }
    }
    if (sawF) return 2;
    if (sawU) return 0;
    return 1;
}
__device__ __forceinline__ bool read_mask(const void* p, int i, int fmt) {
    if (fmt == 0) return ((const unsigned char*)p)[i] != 0;
    if (fmt == 1) return ((const int*)p)[i] != 0;
    return ((const float*)p)[i] != 0.0f;
}

__device__ __forceinline__ unsigned spread4(unsigned x) {
    x &= 15u; x = (x | (x << 2)) & 0x33u; x = (x | (x << 1)) & 0x55u; return x;
}
__device__ __forceinline__ int morton_key(float x, float y) {
    int cx = (int)(x * 16.0f); cx = cx < 0 ? 0 : (cx > 15 ? 15 : cx);
    int cy = (int)(y * 16.0f); cy = cy < 0 ? 0 : (cy > 15 ? 15 : cy);
    return (int)(spread4((unsigned)cx) | (spread4((unsigned)cy) << 1));
}

// ---------------- prep -------------------------------------------------------
__global__ void prep_kernel(const float* __restrict__ slocs,
                            const float* __restrict__ tlocs,
                            const void* __restrict__ smask,
                            const void* __restrict__ tmask) {
    __shared__ int sf[2];
    if (threadIdx.x == 0) {
        sf[0] = detect_fmt((const unsigned*)smask);
        sf[1] = detect_fmt((const unsigned*)tmask);
    }
    __syncthreads();
    int i = blockIdx.x * blockDim.x + threadIdx.x;
    if (blockIdx.x == 0 && threadIdx.x < 3 * Bz) {
        g_cnt0u[threadIdx.x] = 0;
        g_cnt0v[threadIdx.x] = 0;
    }
    if (i >= Bz * Nn) return;
    int b = i / Nn, n = i % Nn;

    bool sok = read_mask(smask, i, sf[0]);
    float sx = slocs[2 * i], sy = slocs[2 * i + 1];
    g_sl0[b][n] = make_float2(sok ? sx : -1e18f, sy);
    g_sok0[b][n] = sok ? 1 : 0;
    g_skey[b][n] = sok ? morton_key(sx, sy) : 256;
    g_v2[b][n] = 0.0f;
    g_ev[b][n] = 1.0f;

    bool tok = read_mask(tmask, i, sf[1]);
    float tx = tlocs[2 * i], ty = tlocs[2 * i + 1];
    g_tl0[b][n] = make_float2(tok ? tx : 1e18f, ty);
    g_tkey[b][n] = tok ? morton_key(tx, ty) : 256;
}

// ---------------- fused bitonic sort + scatter + chunk bboxes -----------------
__global__ __launch_bounds__(1024) void sort_scatter_kernel() {
    __shared__ unsigned sk[4096];
    int side = blockIdx.x, b = blockIdx.y, tid = threadIdx.x;
    int lane = tid & 31;
    for (int i = tid; i < 4096; i += 1024) {
        int key = side ? g_skey[b][i] : g_tkey[b][i];
        sk[i] = ((unsigned)key << 12) | (unsigned)i;
    }
    __syncthreads();
    for (int k = 2; k <= 4096; k <<= 1) {
        for (int j = k >> 1; j >= 1; j >>= 1) {
            for (int i = tid; i < 4096; i += 1024) {
                int l = i ^ j;
                if (l > i) {
                    unsigned a = sk[i], c = sk[l];
                    bool up = ((i & k) == 0);
                    if ((a > c) == up) { sk[i] = c; sk[l] = a; }
                }
            }
            __syncthreads();
        }
    }
    for (int i = tid; i < 4096; i += 1024) {
        int idx = (int)(sk[i] & 0xFFFu);
        float2 p;
        if (side) {
            p = g_sl0[b][idx];
            g_sv4[b][i] = make_float4(p.x, p.y, 0.0f, 0.0f);
            g_sok[b][i] = g_sok0[b][idx];
            g_sperm[b][i] = idx;
        } else {
            p = g_tl0[b][idx];
            g_tu4[b][i] = make_float4(p.x, p.y, 0.0f, 0.0f);
            g_tperm[b][i] = idx;
        }
        float mnx = p.x, mxx = p.x, mny = p.y, mxy = p.y;
        #pragma unroll
        for (int off = 16; off; off >>= 1) {
            mnx = fminf(mnx, __shfl_xor_sync(0xffffffffu, mnx, off));
            mxx = fmaxf(mxx, __shfl_xor_sync(0xffffffffu, mxx, off));
            mny = fminf(mny, __shfl_xor_sync(0xffffffffu, mny, off));
            mxy = fmaxf(mxy, __shfl_xor_sync(0xffffffffu, mxy, off));
        }
        if (lane == 0) {
            int chunk = i >> 5;
            float4 bb = make_float4(mnx, mny, mxx, mxy);
            if (side) g_sbb[b][chunk] = bb; else g_tbb[b][chunk] = bb;
        }
    }
}

// ---------------- build padded CSR (cols + K = exp2(lk2)) once ----------------
__global__ __launch_bounds__(256) void csr_build() {
    const int b = blockIdx.y, side = blockIdx.z;
    const int warp = threadIdx.x >> 5, lane = threadIdx.x & 31;
    const int row = blockIdx.x * 8 + warp;
    const unsigned FULL = 0xffffffffu;
    const float NEG_INV2 = c_NEG_INV2;

    float4 rp = (side == 0) ? g_tu4[b][row] : g_sv4[b][row];
    const float4* opp = (side == 0) ? g_sv4[b] : g_tu4[b];
    const float4* bb  = (side == 0) ? g_sbb[b] : g_tbb[b];
    unsigned short* cseg = ((side == 0) ? g_colT[b] : g_colS[b]) + (size_t)row * RSTRIDE;
    float*          vseg = ((side == 0) ? g_valT[b] : g_valS[b]) + (size_t)row * RSTRIDE;

    int cnt = 0;
    #pragma unroll
    for (int t = 0; t < 4; t++) {
        int c = t * 32 + lane;
        float4 cb = bb[c];
        float ddx = fmaxf(fmaxf(cb.x - rp.x, rp.x - cb.z), 0.0f);
        float ddy = fmaxf(fmaxf(cb.y - rp.y, rp.y - cb.w), 0.0f);
        bool inc = (ddx * ddx + ddy * ddy < 0.0401f);
        unsigned mask = __ballot_sync(FULL, inc);
        while (mask) {
            int chunk = t * 32 + (__ffs(mask) - 1);
            mask &= mask - 1;
            int col = chunk * 32 + lane;
            float4 q = opp[col];
            float dx = __fadd_rn(rp.x, -q.x);
            float dy = __fadd_rn(rp.y, -q.y);
            float d2 = __fadd_rn(__fmul_rn(dx, dx), __fmul_rn(dy, dy));
            bool valid = (d2 < 0.04f);
            unsigned vm = __ballot_sync(FULL, valid);
            if (valid) {
                int slot = cnt + __popc(vm & ((1u << lane) - 1u));
                if (slot < RSTRIDE) {
                    cseg[slot] = (unsigned short)col;
                    vseg[slot] = exp2f(__fmul_rn(d2, NEG_INV2));
                }
            }
            cnt += __popc(vm);
        }
    }
    if (lane == 0) {
        cnt = cnt > RSTRIDE ? RSTRIDE : cnt;
        if (side == 0) { g_nnzT[b][row] = cnt; g_has[b][row] = (cnt > 0) ? 1 : 0; }
        else           { g_nnzS[b][row] = cnt; }
    }
}

// ---------------- LSE pass: pure FMA stream over SoA CSR ----------------------
// grid (4096/8, Bz); block 256 = 8 warps; warp = row
template <int MODE>
__global__ __launch_bounds__(256) void lse_kernel(int iter) {
    const int b = blockIdx.y;
    const int warp = threadIdx.x >> 5, lane = threadIdx.x & 31;
    const int row = blockIdx.x * 8 + warp;
    const unsigned FULL = 0xffffffffu;

    const unsigned short* cseg = ((MODE == 0) ? g_colT[b] : g_colS[b]) + (size_t)row * RSTRIDE;
    const float*          vseg = ((MODE == 0) ? g_valT[b] : g_valS[b]) + (size_t)row * RSTRIDE;
    const float*          ed   = (MODE == 0) ? g_ev[b] : g_eu[b];
    const int cnt = (MODE == 0) ? g_nnzT[b][row] : g_nnzS[b][row];

    float s0 = 0.0f, s1 = 0.0f;
    int i = 2 * lane;
    for (; i + 1 < cnt; i += 64) {
        unsigned cc = *(const unsigned*)(cseg + i);     // 2 cols
        float2 kk = *(const float2*)(vseg + i);          // 2 Ks
        s0 = __fmaf_rn(kk.x, ed[cc & 0xFFFFu], s0);
        s1 = __fmaf_rn(kk.y, ed[cc >> 16], s1);
    }
    if (i < cnt) s0 = __fmaf_rn(vseg[i], ed[cseg[i]], s0);

    float s = s0 + s1;
    #pragma unroll
    for (int off = 16; off; off >>= 1) s += __shfl_xor_sync(FULL, s, off);

    if (lane == 0) {
        if (MODE == 0) {
            float tot = s + ((iter > 0) ? (float)g_cnt0v[(iter - 1) * Bz + b] : 0.0f);
            float u2;
            if (tot > 0.0f) u2 = -log2f(tot);
            else { u2 = BIG2; atomicAdd(&g_cnt0u[iter * Bz + b], 1); }
            g_u2[b][row] = u2;
            g_eu[b][row] = (tot > 0.0f) ? exp2f(u2) : 1.0f;   // never gathered when empty
        } else {
            float tot = s + (float)g_cnt0u[iter * Bz + b];
            bool sok = g_sok[b][row] != 0;
            float v2;
            if (tot > 0.0f) v2 = -log2f(tot);
            else { v2 = BIG2; if (sok) atomicAdd(&g_cnt0v[iter * Bz + b], 1); }
            v2 = sok ? v2 : 0.0f;
            g_v2[b][row] = v2;
            g_ev[b][row] = (tot > 0.0f || !sok) ? exp2f(v2) : 1.0f;
        }
    }
}

// ---------------- feats f32 [b][orig n][c] -> fp16 [b][c][sorted n] ----------
__global__ void feats_transpose(const float* __restrict__ f) {
    __shared__ float tile[32][33];
    int b = blockIdx.z;
    int n0 = blockIdx.x * 32, c0 = blockIdx.y * 32;
    int tx = threadIdx.x, ty = threadIdx.y;
    #pragma unroll
    for (int j = 0; j < 4; j++) {
        int n = n0 + ty + j * 8;
        int on = g_sperm[b][n];
        tile[ty + j * 8][tx] = f[((b * Nn + on) * Cc) + (c0 + tx)];
    }
    __syncthreads();
    #pragma unroll
    for (int j = 0; j < 4; j++) {
        int c = c0 + ty + j * 8;
        g_fT[b][c][n0 + tx] = __float2half(tile[tx][ty + j * 8]);
    }
}

// ---------------- fused attn-recompute GEMM (log2-domain duals) --------------
__device__ __forceinline__ void mma16816(float& c0, float& c1, float& c2, float& c3,
                                         unsigned a0, unsigned a1, unsigned a2, unsigned a3,
                                         unsigned b0, unsigned b1) {
    asm volatile(
        "mma.sync.aligned.m16n8k16.row.col.f32.f16.f16.f32 "
        "{%0,%1,%2,%3}, {%4,%5,%6,%7}, {%8,%9}, {%0,%1,%2,%3};\n"
        : "+f"(c0), "+f"(c1), "+f"(c2), "+f"(c3)
        : "r"(a0), "r"(a1), "r"(a2), "r"(a3), "r"(b0), "r"(b1));
}

__device__ __forceinline__ float attn_val(float txx, float tyy, float uu2, float4 q) {
    float dx = __fadd_rn(txx, -q.x);
    float dy = __fadd_rn(tyy, -q.y);
    float d2 = __fadd_rn(__fmul_rn(dx, dx), __fmul_rn(dy, dy));
    if (d2 < 0.04f)
        return exp2f(__fadd_rn(__fmaf_rn(d2, c_NEG_INV2, uu2), q.z));
    return 0.0f;
}

__device__ __forceinline__ unsigned pack2(float x, float y) {
    __half2 h = __floats2half2_rn(x, y);
    return *reinterpret_cast<unsigned*>(&h);
}

#define GBM 64
#define GBC 128
#define GBK 64
#define SBSTRIDE 72

__global__ __launch_bounds__(128) void gemm_kernel(float* __restrict__ out) {
    const int b  = blockIdx.z;
    const int m0 = blockIdx.x * GBM;
    const int c0 = blockIdx.y * GBC;
    const int warp = threadIdx.x >> 5, lane = threadIdx.x & 31;
    const int gid = lane >> 2, tig = lane & 3;

    __shared__ __align__(16) __half sB[GBC][SBSTRIDE];
    __shared__ __align__(16) float4 sS[GBK];

    float tmnx, tmxx, tmny, tmxy;
    {
        float4 b0 = g_tbb[b][(m0 >> 5) + 0], b1 = g_tbb[b][(m0 >> 5) + 1];
        tmnx = fminf(b0.x, b1.x); tmny = fminf(b0.y, b1.y);
        tmxx = fmaxf(b0.z, b1.z); tmxy = fmaxf(b0.w, b1.w);
    }

    const int rlo = m0 + warp * 16 + gid;
    const int rhi = rlo + 8;
    float4 plo = g_tu4[b][rlo]; plo.z = g_u2[b][rlo];
    float4 phi = g_tu4[b][rhi]; phi.z = g_u2[b][rhi];
    const bool haslo = g_has[b][rlo] != 0;
    const bool hashi = g_has[b][rhi] != 0;

    float acc[16][4];
    #pragma unroll
    for (int j = 0; j < 16; j++) {
        acc[j][0] = 0.f; acc[j][1] = 0.f; acc[j][2] = 0.f; acc[j][3] = 0.f;
    }

    for (int n0 = 0; n0 < Nn; n0 += GBK) {
        {
            float4 s0 = g_sbb[b][(n0 >> 5) + 0], s1 = g_sbb[b][(n0 >> 5) + 1];
            float smnx = fminf(s0.x, s1.x), smny = fminf(s0.y, s1.y);
            float smxx = fmaxf(s0.z, s1.z), smxy = fmaxf(s0.w, s1.w);
            float ddx = fmaxf(fmaxf(smnx - tmxx, tmnx - smxx), 0.0f);
            float ddy = fmaxf(fmaxf(smny - tmxy, tmny - smxy), 0.0f);
            if (ddx * ddx + ddy * ddy >= 0.0401f) continue;
        }
        __syncthreads();
        {
            int idx = threadIdx.x;
            #pragma unroll
            for (int t = 0; t < 8; t++, idx += 128) {
                int row = idx >> 3, ch = idx & 7;
                const uint4* src = reinterpret_cast<const uint4*>(&g_fT[b][c0 + row][n0]) + ch;
                *reinterpret_cast<uint4*>(&sB[row][ch * 8]) = *src;
            }
        }
        if (threadIdx.x < GBK) {
            int n = n0 + threadIdx.x;
            float4 p = g_sv4[b][n];
            p.z = g_v2[b][n];
            sS[threadIdx.x] = p;
        }
        __syncthreads();

        #pragma unroll
        for (int kf = 0; kf < 4; kf++) {
            const int kb = kf * 16 + 2 * tig;
            float4 qa = sS[kb];
            float4 qb = sS[kb + 1];
            float4 qc = sS[kb + 8];
            float4 qd = sS[kb + 9];

            unsigned a0 = pack2(attn_val(plo.x, plo.y, plo.z, qa), attn_val(plo.x, plo.y, plo.z, qb));
            unsigned a1 = pack2(attn_val(phi.x, phi.y, phi.z, qa), attn_val(phi.x, phi.y, phi.z, qb));
            unsigned a2 = pack2(attn_val(plo.x, plo.y, plo.z, qc), attn_val(plo.x, plo.y, plo.z, qd));
            unsigned a3 = pack2(attn_val(phi.x, phi.y, phi.z, qc), attn_val(phi.x, phi.y, phi.z, qd));

            #pragma unroll
            for (int j = 0; j < 16; j++) {
                const __half* brow = &sB[j * 8 + gid][kf * 16 + 2 * tig];
                unsigned b0 = *reinterpret_cast<const unsigned*>(brow);
                unsigned b1 = *reinterpret_cast<const unsigned*>(brow + 8);
                mma16816(acc[j][0], acc[j][1], acc[j][2], acc[j][3],
                         a0, a1, a2, a3, b0, b1);
            }
        }
    }

    const int orlo = g_tperm[b][rlo];
    const int orhi = g_tperm[b][rhi];
    #pragma unroll
    for (int j = 0; j < 16; j++) {
        int c = c0 + j * 8 + 2 * tig;
        float2 vlo = haslo ? make_float2(acc[j][0], acc[j][1]) : make_float2(0.f, 0.f);
        float2 vhi = hashi ? make_float2(acc[j][2], acc[j][3]) : make_float2(0.f, 0.f);
        *reinterpret_cast<float2*>(&out[((b * Mm + orlo) * Cc) + c]) = vlo;
        *reinterpret_cast<float2*>(&out[((b * Mm + orhi) * Cc) + c]) = vhi;
    }
}

// ------------------------------- launch ---------------------------------------
extern "C" void kernel_launch(void* const* d_in, const int* in_sizes, int n_in,
                              void* d_out, int out_size) {
    const float* feats = (const float*)d_in[0];
    const float* slocs = (const float*)d_in[1];
    const float* tlocs = (const float*)d_in[2];
    const void*  smask = d_in[3];
    const void*  tmask = d_in[4];
    float* out = (float*)d_out;

    prep_kernel<<<(Bz * Nn + 255) / 256, 256>>>(slocs, tlocs, smask, tmask);   // 1
    sort_scatter_kernel<<<dim3(2, Bz), 1024>>>();                               // 2
    csr_build<<<dim3(4096 / 8, Bz, 2), 256>>>();                                // 3

    for (int it = 0; it < 3; it++) {
        lse_kernel<0><<<dim3(4096 / 8, Bz), 256>>>(it);                         // 4 <- profiled
        lse_kernel<1><<<dim3(4096 / 8, Bz), 256>>>(it);
    }

    feats_transpose<<<dim3(Nn / 32, Cc / 32, Bz), dim3(32, 8)>>>(feats);
    gemm_kernel<<<dim3(Mm / GBM, Cc / GBC, Bz), 128>>>(out);
}